// round 12
// baseline (speedup 1.0000x reference)
#include <cuda_runtime.h>
#include <cuda_bf16.h>
#include <math.h>
#include <stdint.h>

// Problem constants
static constexpr int BB   = 4;
static constexpr int SS   = 2048;
static constexpr int DM   = 768;
static constexpr int HH   = 12;
static constexpr int DH   = 64;
static constexpr int NTOK = BB * SS;          // 8192
static constexpr float EPS = 1e-5f;

// Scratch (device globals: no allocation)
__device__ float g_Q  [NTOK * DM];
__device__ float g_K  [NTOK * DM];
__device__ float g_V  [NTOK * DM];
__device__ float g_Ctx[NTOK * DM];
__device__ float g_Hid[NTOK * 2 * DM];
__device__ float g_H  [NTOK * DM];

// ---------------------------------------------------------------------------
// TF32 / cp.async helpers
// ---------------------------------------------------------------------------
__device__ __forceinline__ float tf32r(float x) {
    uint32_t u;
    asm("cvt.rna.tf32.f32 %0, %1;" : "=r"(u) : "f"(x));
    return __uint_as_float(u);
}

__device__ __forceinline__ void cp_async8(uint32_t dst, const void* src) {
    asm volatile("cp.async.ca.shared.global [%0], [%1], 8;\n" :: "r"(dst), "l"(src));
}
__device__ __forceinline__ void cp_async16(uint32_t dst, const void* src) {
    asm volatile("cp.async.cg.shared.global [%0], [%1], 16;\n" :: "r"(dst), "l"(src));
}
__device__ __forceinline__ void cp_commit() {
    asm volatile("cp.async.commit_group;\n" ::: "memory");
}
__device__ __forceinline__ void cp_wait0() {
    asm volatile("cp.async.wait_group 0;\n" ::: "memory");
}

// D(16x8) += A(16x8) * B(8x8)  tf32 inputs, fp32 accum.
__device__ __forceinline__ void mma8(float* c, const float* a, const float* b) {
    asm volatile(
        "mma.sync.aligned.m16n8k8.row.col.f32.tf32.tf32.f32 "
        "{%0,%1,%2,%3}, {%4,%5,%6,%7}, {%8,%9}, {%0,%1,%2,%3};\n"
        : "+f"(c[0]), "+f"(c[1]), "+f"(c[2]), "+f"(c[3])
        : "r"(__float_as_uint(a[0])), "r"(__float_as_uint(a[1])),
          "r"(__float_as_uint(a[2])), "r"(__float_as_uint(a[3])),
          "r"(__float_as_uint(b[0])), "r"(__float_as_uint(b[1])));
}

// ---------------------------------------------------------------------------
// TF32 tensor-core GEMM with 2-stage cp.async pipeline.
// C[M,N] = A[M,K] @ W[K,N] + bias, fused epilogue.
// EPI = 0: bias; 1: bias + ReLU; 2: bias + residual.
// CTA 128x128, 8 warps (4x2), warp tile 32x64, BK=16.
// ---------------------------------------------------------------------------
template <int EPI>
__global__ __launch_bounds__(256) void gemm_tc(
    const float* __restrict__ A, const float* __restrict__ W,
    const float* __restrict__ bias, const float* __restrict__ res,
    float* __restrict__ C, int M, int N, int K)
{
    __shared__ float As[2][128][20];    // raw f32; pad 20 -> conflict-free frags
    __shared__ float Bs[2][16][136];

    const int tid  = threadIdx.x;
    const int lane = tid & 31;
    const int wid  = tid >> 5;
    const int g    = lane >> 2;
    const int t    = lane & 3;
    const int wm   = wid & 3;
    const int wn   = wid >> 2;
    const int m0   = blockIdx.y * 128;
    const int n0   = blockIdx.x * 128;

    float c[2][8][4];
#pragma unroll
    for (int mf = 0; mf < 2; mf++)
#pragma unroll
        for (int nf = 0; nf < 8; nf++)
#pragma unroll
            for (int i = 0; i < 4; i++) c[mf][nf][i] = 0.f;

    // cp.async copy indices
    // A slab: 128 rows x 16 cols -> 8B chunks: id = row*8 + cpair
    // B slab: 16 rows x 128 cols -> 16B chunks: id = row*32 + c4
    uint32_t a_smem[4], b_smem[2];
    const float* a_gptr[4];
    const float* b_gptr[2];
#pragma unroll
    for (int j = 0; j < 4; j++) {
        int id = tid + 256 * j;
        int row = id >> 3, cp = id & 7;
        a_smem[j] = (uint32_t)__cvta_generic_to_shared(&As[0][row][cp * 2]);
        a_gptr[j] = A + (size_t)(m0 + row) * K + cp * 2;
    }
#pragma unroll
    for (int j = 0; j < 2; j++) {
        int id = tid + 256 * j;
        int row = id >> 5, c4 = id & 31;
        b_smem[j] = (uint32_t)__cvta_generic_to_shared(&Bs[0][row][c4 * 4]);
        b_gptr[j] = W + (size_t)row * N + n0 + c4 * 4;
    }
    const uint32_t aStage = (uint32_t)(sizeof(float) * 128 * 20);
    const uint32_t bStage = (uint32_t)(sizeof(float) * 16 * 136);

    // prologue: issue slab 0 into buffer 0
#pragma unroll
    for (int j = 0; j < 4; j++) cp_async8(a_smem[j], a_gptr[j]);
#pragma unroll
    for (int j = 0; j < 2; j++) cp_async16(b_smem[j], b_gptr[j]);
    cp_commit();

    const int nslab = K >> 4;
    for (int i = 0; i < nslab; i++) {
        cp_wait0();
        __syncthreads();

        const int cb = i & 1;
        if (i + 1 < nslab) {
            const int nb = (i + 1) & 1;
            const int kt = (i + 1) << 4;
#pragma unroll
            for (int j = 0; j < 4; j++)
                cp_async8(a_smem[j] + nb * aStage, a_gptr[j] + kt);
#pragma unroll
            for (int j = 0; j < 2; j++)
                cp_async16(b_smem[j] + nb * bStage, b_gptr[j] + (size_t)kt * N);
            cp_commit();
        }

#pragma unroll
        for (int kk = 0; kk < 2; kk++) {
            float a[2][4];
#pragma unroll
            for (int mf = 0; mf < 2; mf++) {
                const int r = wm * 32 + mf * 16;
                a[mf][0] = tf32r(As[cb][r + g    ][kk * 8 + t    ]);
                a[mf][1] = tf32r(As[cb][r + g + 8][kk * 8 + t    ]);
                a[mf][2] = tf32r(As[cb][r + g    ][kk * 8 + t + 4]);
                a[mf][3] = tf32r(As[cb][r + g + 8][kk * 8 + t + 4]);
            }
            float b[8][2];
#pragma unroll
            for (int nf = 0; nf < 8; nf++) {
                const int cc = wn * 64 + nf * 8 + g;
                b[nf][0] = tf32r(Bs[cb][kk * 8 + t    ][cc]);
                b[nf][1] = tf32r(Bs[cb][kk * 8 + t + 4][cc]);
            }
#pragma unroll
            for (int mf = 0; mf < 2; mf++)
#pragma unroll
                for (int nf = 0; nf < 8; nf++)
                    mma8(c[mf][nf], a[mf], b[nf]);
        }
    }

    // Epilogue
#pragma unroll
    for (int mf = 0; mf < 2; mf++) {
        const int r0 = m0 + wm * 32 + mf * 16 + g;
#pragma unroll
        for (int nf = 0; nf < 8; nf++) {
            const int cc = n0 + wn * 64 + nf * 8 + 2 * t;
            float2 bb = *(const float2*)(bias + cc);
            float v0 = c[mf][nf][0] + bb.x;
            float v1 = c[mf][nf][1] + bb.y;
            float v2 = c[mf][nf][2] + bb.x;
            float v3 = c[mf][nf][3] + bb.y;
            if (EPI == 1) {
                v0 = fmaxf(v0, 0.f); v1 = fmaxf(v1, 0.f);
                v2 = fmaxf(v2, 0.f); v3 = fmaxf(v3, 0.f);
            }
            if (EPI == 2) {
                float2 r0v = *(const float2*)(res + (size_t)r0 * N + cc);
                float2 r1v = *(const float2*)(res + (size_t)(r0 + 8) * N + cc);
                v0 += r0v.x; v1 += r0v.y; v2 += r1v.x; v3 += r1v.y;
            }
            *(float2*)(C + (size_t)r0 * N + cc)       = make_float2(v0, v1);
            *(float2*)(C + (size_t)(r0 + 8) * N + cc) = make_float2(v2, v3);
        }
    }
}

// ---------------------------------------------------------------------------
// Flash attention with TF32 mma. One CTA per (b, h, 128-row q tile).
// 128 threads = 4 warps; each warp owns 32 q rows (2 mf tiles of 16).
// K/V B-fragments are reused across both mf tiles -> ~1.6x less smem traffic.
// ---------------------------------------------------------------------------
__global__ __launch_bounds__(128) void attn_tc(
    const float* __restrict__ Q, const float* __restrict__ K,
    const float* __restrict__ V, float* __restrict__ Ctx)
{
    extern __shared__ float sm[];
    float* Qs = sm;                       // 128 x 68
    float* Ks = Qs + 128 * 68;            // 64 x 68
    float* Vs = Ks + 64 * 68;             // 64 x 72
    float* Ps = Vs + 64 * 72;             // 4 warps x 32 x 68

    const int tid  = threadIdx.x;
    const int lane = tid & 31;
    const int wid  = tid >> 5;
    const int g    = lane >> 2;
    const int t    = lane & 3;
    const int b    = blockIdx.z;
    const int h    = blockIdx.y;
    const int q0   = blockIdx.x * 128;
    const int qr   = wid * 32;            // warp's q-row base within tile
    float* Pw = Ps + wid * 32 * 68;

    // Load Q tile (128 x 64), scale by 1/8, convert tf32
#pragma unroll
    for (int ii = 0; ii < 16; ii++) {
        int idx = tid + 128 * ii;
        int row = idx >> 4, c4 = (idx & 15) * 4;
        float4 v = *(const float4*)(Q + ((size_t)(b * SS + q0 + row) * DM + h * DH + c4));
        Qs[row * 68 + c4 + 0] = tf32r(v.x * 0.125f);
        Qs[row * 68 + c4 + 1] = tf32r(v.y * 0.125f);
        Qs[row * 68 + c4 + 2] = tf32r(v.z * 0.125f);
        Qs[row * 68 + c4 + 3] = tf32r(v.w * 0.125f);
    }

    float o[2][8][4];
#pragma unroll
    for (int mf = 0; mf < 2; mf++)
#pragma unroll
        for (int nf = 0; nf < 8; nf++)
#pragma unroll
            for (int i = 0; i < 4; i++) o[mf][nf][i] = 0.f;
    float mrow[4] = {-1e30f, -1e30f, -1e30f, -1e30f};
    float lrow[4] = {0.f, 0.f, 0.f, 0.f};

    for (int k0 = 0; k0 < SS; k0 += 64) {
        __syncthreads();
#pragma unroll
        for (int ii = 0; ii < 8; ii++) {
            int idx = tid + 128 * ii;
            int row = idx >> 4, c4 = (idx & 15) * 4;
            size_t gb = (size_t)(b * SS + k0 + row) * DM + h * DH + c4;
            float4 kv = *(const float4*)(K + gb);
            float4 vv = *(const float4*)(V + gb);
            Ks[row * 68 + c4 + 0] = tf32r(kv.x);
            Ks[row * 68 + c4 + 1] = tf32r(kv.y);
            Ks[row * 68 + c4 + 2] = tf32r(kv.z);
            Ks[row * 68 + c4 + 3] = tf32r(kv.w);
            Vs[row * 72 + c4 + 0] = tf32r(vv.x);
            Vs[row * 72 + c4 + 1] = tf32r(vv.y);
            Vs[row * 72 + c4 + 2] = tf32r(vv.z);
            Vs[row * 72 + c4 + 3] = tf32r(vv.w);
        }
        __syncthreads();

        // S = Q @ K^T (already scaled). s[mf][nf][4]
        float s[2][8][4];
#pragma unroll
        for (int mf = 0; mf < 2; mf++)
#pragma unroll
            for (int nf = 0; nf < 8; nf++)
#pragma unroll
                for (int i = 0; i < 4; i++) s[mf][nf][i] = 0.f;

#pragma unroll
        for (int kk = 0; kk < 8; kk++) {
            float a[2][4];
#pragma unroll
            for (int mf = 0; mf < 2; mf++) {
                const int r = qr + mf * 16;
                a[mf][0] = Qs[(r + g    ) * 68 + kk * 8 + t    ];
                a[mf][1] = Qs[(r + g + 8) * 68 + kk * 8 + t    ];
                a[mf][2] = Qs[(r + g    ) * 68 + kk * 8 + t + 4];
                a[mf][3] = Qs[(r + g + 8) * 68 + kk * 8 + t + 4];
            }
#pragma unroll
            for (int nf = 0; nf < 8; nf++) {
                float bfr[2];
                bfr[0] = Ks[(nf * 8 + g) * 68 + kk * 8 + t    ];
                bfr[1] = Ks[(nf * 8 + g) * 68 + kk * 8 + t + 4];
                mma8(s[0][nf], a[0], bfr);
                mma8(s[1][nf], a[1], bfr);
            }
        }

        // Online softmax per mf tile (rows qr+mf*16+g and +8)
#pragma unroll
        for (int mf = 0; mf < 2; mf++) {
            float mx0 = -1e30f, mx1 = -1e30f;
#pragma unroll
            for (int nf = 0; nf < 8; nf++) {
                mx0 = fmaxf(mx0, fmaxf(s[mf][nf][0], s[mf][nf][1]));
                mx1 = fmaxf(mx1, fmaxf(s[mf][nf][2], s[mf][nf][3]));
            }
            mx0 = fmaxf(mx0, __shfl_xor_sync(0xffffffffu, mx0, 1));
            mx0 = fmaxf(mx0, __shfl_xor_sync(0xffffffffu, mx0, 2));
            mx1 = fmaxf(mx1, __shfl_xor_sync(0xffffffffu, mx1, 1));
            mx1 = fmaxf(mx1, __shfl_xor_sync(0xffffffffu, mx1, 2));

            float mn0 = fmaxf(mrow[mf * 2    ], mx0);
            float mn1 = fmaxf(mrow[mf * 2 + 1], mx1);
            float cr0 = __expf(mrow[mf * 2    ] - mn0);
            float cr1 = __expf(mrow[mf * 2 + 1] - mn1);
            mrow[mf * 2] = mn0; mrow[mf * 2 + 1] = mn1;

            float sum0 = 0.f, sum1 = 0.f;
#pragma unroll
            for (int nf = 0; nf < 8; nf++) {
                s[mf][nf][0] = __expf(s[mf][nf][0] - mn0);
                s[mf][nf][1] = __expf(s[mf][nf][1] - mn0);
                s[mf][nf][2] = __expf(s[mf][nf][2] - mn1);
                s[mf][nf][3] = __expf(s[mf][nf][3] - mn1);
                sum0 += s[mf][nf][0] + s[mf][nf][1];
                sum1 += s[mf][nf][2] + s[mf][nf][3];
            }
            sum0 += __shfl_xor_sync(0xffffffffu, sum0, 1);
            sum0 += __shfl_xor_sync(0xffffffffu, sum0, 2);
            sum1 += __shfl_xor_sync(0xffffffffu, sum1, 1);
            sum1 += __shfl_xor_sync(0xffffffffu, sum1, 2);
            lrow[mf * 2]     = lrow[mf * 2]     * cr0 + sum0;
            lrow[mf * 2 + 1] = lrow[mf * 2 + 1] * cr1 + sum1;

#pragma unroll
            for (int nf = 0; nf < 8; nf++) {
                o[mf][nf][0] *= cr0; o[mf][nf][1] *= cr0;
                o[mf][nf][2] *= cr1; o[mf][nf][3] *= cr1;
                Pw[(mf * 16 + g    ) * 68 + nf * 8 + 2 * t    ] = tf32r(s[mf][nf][0]);
                Pw[(mf * 16 + g    ) * 68 + nf * 8 + 2 * t + 1] = tf32r(s[mf][nf][1]);
                Pw[(mf * 16 + g + 8) * 68 + nf * 8 + 2 * t    ] = tf32r(s[mf][nf][2]);
                Pw[(mf * 16 + g + 8) * 68 + nf * 8 + 2 * t + 1] = tf32r(s[mf][nf][3]);
            }
        }
        __syncwarp();

        // O += P @ V (V B-frags reused across both mf tiles)
#pragma unroll
        for (int kk = 0; kk < 8; kk++) {
            float a[2][4];
#pragma unroll
            for (int mf = 0; mf < 2; mf++) {
                const int r = mf * 16;
                a[mf][0] = Pw[(r + g    ) * 68 + kk * 8 + t    ];
                a[mf][1] = Pw[(r + g + 8) * 68 + kk * 8 + t    ];
                a[mf][2] = Pw[(r + g    ) * 68 + kk * 8 + t + 4];
                a[mf][3] = Pw[(r + g + 8) * 68 + kk * 8 + t + 4];
            }
#pragma unroll
            for (int nf = 0; nf < 8; nf++) {
                float bfr[2];
                bfr[0] = Vs[(kk * 8 + t    ) * 72 + nf * 8 + g];
                bfr[1] = Vs[(kk * 8 + t + 4) * 72 + nf * 8 + g];
                mma8(o[0][nf], a[0], bfr);
                mma8(o[1][nf], a[1], bfr);
            }
        }
        __syncwarp();
    }

    // Finalize, store context tokens
#pragma unroll
    for (int mf = 0; mf < 2; mf++) {
        const float inv0 = 1.f / lrow[mf * 2];
        const float inv1 = 1.f / lrow[mf * 2 + 1];
        const int row0 = b * SS + q0 + qr + mf * 16 + g;
#pragma unroll
        for (int nf = 0; nf < 8; nf++) {
            const int cc = h * DH + nf * 8 + 2 * t;
            *(float2*)(Ctx + (size_t)row0 * DM + cc) =
                make_float2(o[mf][nf][0] * inv0, o[mf][nf][1] * inv0);
            *(float2*)(Ctx + (size_t)(row0 + 8) * DM + cc) =
                make_float2(o[mf][nf][2] * inv1, o[mf][nf][3] * inv1);
        }
    }
}

// ---------------------------------------------------------------------------
// LayerNorm over last dim (768), one block per token row.
// ---------------------------------------------------------------------------
__global__ __launch_bounds__(256) void ln_kernel(
    const float* __restrict__ Hbuf, const float* __restrict__ gamma,
    const float* __restrict__ beta, float* __restrict__ out)
{
    __shared__ float red[16];
    const int row = blockIdx.x;
    const float* hp = Hbuf + (size_t)row * DM;

    float v[3];
    float sum = 0.f, sq = 0.f;
#pragma unroll
    for (int i = 0; i < 3; i++) {
        v[i] = hp[threadIdx.x + 256 * i];
        sum += v[i];
        sq  += v[i] * v[i];
    }
#pragma unroll
    for (int off = 16; off > 0; off >>= 1) {
        sum += __shfl_xor_sync(0xffffffffu, sum, off);
        sq  += __shfl_xor_sync(0xffffffffu, sq,  off);
    }
    const int wid = threadIdx.x >> 5, lane = threadIdx.x & 31;
    if (lane == 0) { red[wid] = sum; red[8 + wid] = sq; }
    __syncthreads();
    float ts = 0.f, tq = 0.f;
#pragma unroll
    for (int w = 0; w < 8; w++) { ts += red[w]; tq += red[8 + w]; }

    const float mean = ts * (1.f / (float)DM);
    const float var  = tq * (1.f / (float)DM) - mean * mean;
    const float rstd = rsqrtf(var + EPS);

#pragma unroll
    for (int i = 0; i < 3; i++) {
        int cIdx = threadIdx.x + 256 * i;
        out[(size_t)row * DM + cIdx] = (v[i] - mean) * rstd * gamma[cIdx] + beta[cIdx];
    }
}

// ---------------------------------------------------------------------------
// Launch
// ---------------------------------------------------------------------------
extern "C" void kernel_launch(void* const* d_in, const int* in_sizes, int n_in,
                              void* d_out, int out_size)
{
    const float* x     = (const float*)d_in[0];
    const float* Wq    = (const float*)d_in[1];
    const float* bq    = (const float*)d_in[2];
    const float* Wk    = (const float*)d_in[3];
    const float* bk    = (const float*)d_in[4];
    const float* Wv    = (const float*)d_in[5];
    const float* bv    = (const float*)d_in[6];
    const float* W1    = (const float*)d_in[7];
    const float* b1    = (const float*)d_in[8];
    const float* W2    = (const float*)d_in[9];
    const float* b2    = (const float*)d_in[10];
    const float* gamma = (const float*)d_in[11];
    const float* beta  = (const float*)d_in[12];
    float* out = (float*)d_out;

    void *pQ, *pK, *pV, *pCtx, *pHid, *pH;
    cudaGetSymbolAddress(&pQ,   g_Q);
    cudaGetSymbolAddress(&pK,   g_K);
    cudaGetSymbolAddress(&pV,   g_V);
    cudaGetSymbolAddress(&pCtx, g_Ctx);
    cudaGetSymbolAddress(&pHid, g_Hid);
    cudaGetSymbolAddress(&pH,   g_H);

    // attn smem: Qs 128*68 + Ks 64*68 + Vs 64*72 + Ps 4*32*68 floats = 105472 B
    const int smem_attn = (128 * 68 + 64 * 68 + 64 * 72 + 4 * 32 * 68) * (int)sizeof(float);
    cudaFuncSetAttribute(attn_tc, cudaFuncAttributeMaxDynamicSharedMemorySize,
                         smem_attn);

    dim3 blk(256);

    // QKV projections (tf32 tensor cores, cp.async pipeline)
    dim3 gQKV(DM / 128, NTOK / 128);  // (6, 64)
    gemm_tc<0><<<gQKV, blk>>>(x, Wq, bq, nullptr, (float*)pQ, NTOK, DM, DM);
    gemm_tc<0><<<gQKV, blk>>>(x, Wk, bk, nullptr, (float*)pK, NTOK, DM, DM);
    gemm_tc<0><<<gQKV, blk>>>(x, Wv, bv, nullptr, (float*)pV, NTOK, DM, DM);

    // Attention: q-tile 128 per CTA
    dim3 gAttn(SS / 128, HH, BB);     // (16, 12, 4)
    attn_tc<<<gAttn, dim3(128), smem_attn>>>((const float*)pQ, (const float*)pK,
                                             (const float*)pV, (float*)pCtx);

    // MLP
    dim3 gM1(2 * DM / 128, NTOK / 128);  // (12, 64)
    gemm_tc<1><<<gM1, blk>>>((const float*)pCtx, W1, b1, nullptr,
                             (float*)pHid, NTOK, 2 * DM, DM);
    dim3 gM2(DM / 128, NTOK / 128);      // (6, 64)
    gemm_tc<2><<<gM2, blk>>>((const float*)pHid, W2, b2, x,
                             (float*)pH, NTOK, DM, 2 * DM);

    // LayerNorm -> output
    ln_kernel<<<NTOK, blk>>>((const float*)pH, gamma, beta, out);
}

// round 13
// speedup vs baseline: 1.0001x; 1.0001x over previous
#include <cuda_runtime.h>
#include <cuda_bf16.h>
#include <math.h>
#include <stdint.h>

// Problem constants
static constexpr int BB   = 4;
static constexpr int SS   = 2048;
static constexpr int DM   = 768;
static constexpr int HH   = 12;
static constexpr int DH   = 64;
static constexpr int NTOK = BB * SS;          // 8192
static constexpr float EPS = 1e-5f;

// Scratch (device globals: no allocation)
__device__ float g_Q  [NTOK * DM];
__device__ float g_K  [NTOK * DM];
__device__ float g_V  [NTOK * DM];
__device__ float g_Ctx[NTOK * DM];
__device__ float g_Hid[NTOK * 2 * DM];
__device__ float g_H  [NTOK * DM];

// ---------------------------------------------------------------------------
// TF32 / cp.async helpers
// ---------------------------------------------------------------------------
__device__ __forceinline__ float tf32r(float x) {
    uint32_t u;
    asm("cvt.rna.tf32.f32 %0, %1;" : "=r"(u) : "f"(x));
    return __uint_as_float(u);
}

__device__ __forceinline__ void cp_async8(uint32_t dst, const void* src) {
    asm volatile("cp.async.ca.shared.global [%0], [%1], 8;\n" :: "r"(dst), "l"(src));
}
__device__ __forceinline__ void cp_async16(uint32_t dst, const void* src) {
    asm volatile("cp.async.cg.shared.global [%0], [%1], 16;\n" :: "r"(dst), "l"(src));
}
__device__ __forceinline__ void cp_commit() {
    asm volatile("cp.async.commit_group;\n" ::: "memory");
}
__device__ __forceinline__ void cp_wait0() {
    asm volatile("cp.async.wait_group 0;\n" ::: "memory");
}

// D(16x8) += A(16x8) * B(8x8)  tf32 inputs, fp32 accum.
__device__ __forceinline__ void mma8(float* c, const float* a, const float* b) {
    asm volatile(
        "mma.sync.aligned.m16n8k8.row.col.f32.tf32.tf32.f32 "
        "{%0,%1,%2,%3}, {%4,%5,%6,%7}, {%8,%9}, {%0,%1,%2,%3};\n"
        : "+f"(c[0]), "+f"(c[1]), "+f"(c[2]), "+f"(c[3])
        : "r"(__float_as_uint(a[0])), "r"(__float_as_uint(a[1])),
          "r"(__float_as_uint(a[2])), "r"(__float_as_uint(a[3])),
          "r"(__float_as_uint(b[0])), "r"(__float_as_uint(b[1])));
}

// ---------------------------------------------------------------------------
// TF32 tensor-core GEMM with 2-stage cp.async pipeline.
// C[M,N] = A[M,K] @ W[K,N] + bias, fused epilogue.
// EPI = 0: bias; 1: bias + ReLU; 2: bias + residual.
// CTA 128x128, 8 warps (4x2), warp tile 32x64, BK=16.
// __launch_bounds__(256, 2): force 2 CTAs/SM (4 warps/SMSP) to hide latency.
// ---------------------------------------------------------------------------
template <int EPI>
__global__ __launch_bounds__(256, 2) void gemm_tc(
    const float* __restrict__ A, const float* __restrict__ W,
    const float* __restrict__ bias, const float* __restrict__ res,
    float* __restrict__ C, int M, int N, int K)
{
    __shared__ float As[2][128][20];    // raw f32; pad 20 -> conflict-free frags
    __shared__ float Bs[2][16][136];

    const int tid  = threadIdx.x;
    const int lane = tid & 31;
    const int wid  = tid >> 5;
    const int g    = lane >> 2;
    const int t    = lane & 3;
    const int wm   = wid & 3;
    const int wn   = wid >> 2;
    const int m0   = blockIdx.y * 128;
    const int n0   = blockIdx.x * 128;

    float c[2][8][4];
#pragma unroll
    for (int mf = 0; mf < 2; mf++)
#pragma unroll
        for (int nf = 0; nf < 8; nf++)
#pragma unroll
            for (int i = 0; i < 4; i++) c[mf][nf][i] = 0.f;

    uint32_t a_smem[4], b_smem[2];
    const float* a_gptr[4];
    const float* b_gptr[2];
#pragma unroll
    for (int j = 0; j < 4; j++) {
        int id = tid + 256 * j;
        int row = id >> 3, cp = id & 7;
        a_smem[j] = (uint32_t)__cvta_generic_to_shared(&As[0][row][cp * 2]);
        a_gptr[j] = A + (size_t)(m0 + row) * K + cp * 2;
    }
#pragma unroll
    for (int j = 0; j < 2; j++) {
        int id = tid + 256 * j;
        int row = id >> 5, c4 = id & 31;
        b_smem[j] = (uint32_t)__cvta_generic_to_shared(&Bs[0][row][c4 * 4]);
        b_gptr[j] = W + (size_t)row * N + n0 + c4 * 4;
    }
    const uint32_t aStage = (uint32_t)(sizeof(float) * 128 * 20);
    const uint32_t bStage = (uint32_t)(sizeof(float) * 16 * 136);

    // prologue: issue slab 0 into buffer 0
#pragma unroll
    for (int j = 0; j < 4; j++) cp_async8(a_smem[j], a_gptr[j]);
#pragma unroll
    for (int j = 0; j < 2; j++) cp_async16(b_smem[j], b_gptr[j]);
    cp_commit();

    const int nslab = K >> 4;
    for (int i = 0; i < nslab; i++) {
        cp_wait0();
        __syncthreads();

        const int cb = i & 1;
        if (i + 1 < nslab) {
            const int nb = (i + 1) & 1;
            const int kt = (i + 1) << 4;
#pragma unroll
            for (int j = 0; j < 4; j++)
                cp_async8(a_smem[j] + nb * aStage, a_gptr[j] + kt);
#pragma unroll
            for (int j = 0; j < 2; j++)
                cp_async16(b_smem[j] + nb * bStage, b_gptr[j] + (size_t)kt * N);
            cp_commit();
        }

#pragma unroll
        for (int kk = 0; kk < 2; kk++) {
            float a[2][4];
#pragma unroll
            for (int mf = 0; mf < 2; mf++) {
                const int r = wm * 32 + mf * 16;
                a[mf][0] = tf32r(As[cb][r + g    ][kk * 8 + t    ]);
                a[mf][1] = tf32r(As[cb][r + g + 8][kk * 8 + t    ]);
                a[mf][2] = tf32r(As[cb][r + g    ][kk * 8 + t + 4]);
                a[mf][3] = tf32r(As[cb][r + g + 8][kk * 8 + t + 4]);
            }
            float b[8][2];
#pragma unroll
            for (int nf = 0; nf < 8; nf++) {
                const int cc = wn * 64 + nf * 8 + g;
                b[nf][0] = tf32r(Bs[cb][kk * 8 + t    ][cc]);
                b[nf][1] = tf32r(Bs[cb][kk * 8 + t + 4][cc]);
            }
#pragma unroll
            for (int mf = 0; mf < 2; mf++)
#pragma unroll
                for (int nf = 0; nf < 8; nf++)
                    mma8(c[mf][nf], a[mf], b[nf]);
        }
    }

    // Epilogue
#pragma unroll
    for (int mf = 0; mf < 2; mf++) {
        const int r0 = m0 + wm * 32 + mf * 16 + g;
#pragma unroll
        for (int nf = 0; nf < 8; nf++) {
            const int cc = n0 + wn * 64 + nf * 8 + 2 * t;
            float2 bb = *(const float2*)(bias + cc);
            float v0 = c[mf][nf][0] + bb.x;
            float v1 = c[mf][nf][1] + bb.y;
            float v2 = c[mf][nf][2] + bb.x;
            float v3 = c[mf][nf][3] + bb.y;
            if (EPI == 1) {
                v0 = fmaxf(v0, 0.f); v1 = fmaxf(v1, 0.f);
                v2 = fmaxf(v2, 0.f); v3 = fmaxf(v3, 0.f);
            }
            if (EPI == 2) {
                float2 r0v = *(const float2*)(res + (size_t)r0 * N + cc);
                float2 r1v = *(const float2*)(res + (size_t)(r0 + 8) * N + cc);
                v0 += r0v.x; v1 += r0v.y; v2 += r1v.x; v3 += r1v.y;
            }
            *(float2*)(C + (size_t)r0 * N + cc)       = make_float2(v0, v1);
            *(float2*)(C + (size_t)(r0 + 8) * N + cc) = make_float2(v2, v3);
        }
    }
}

// ---------------------------------------------------------------------------
// Flash attention with TF32 mma. One CTA per (b, h, 256-row q tile).
// 256 threads = 8 warps; each warp owns 32 q rows (2 mf tiles of 16).
// K/V tiles double-buffered via cp.async (raw f32; tf32 rounding at frag load).
// ---------------------------------------------------------------------------
__global__ __launch_bounds__(256, 1) void attn_tc(
    const float* __restrict__ Q, const float* __restrict__ K,
    const float* __restrict__ V, float* __restrict__ Ctx)
{
    extern __shared__ float sm[];
    float* Qs = sm;                       // 256 x 68  (tf32, pre-scaled)
    float* Ks = Qs + 256 * 68;            // 2 x 64 x 68 (raw f32)
    float* Vs = Ks + 2 * 64 * 68;         // 2 x 64 x 72 (raw f32)
    float* Ps = Vs + 2 * 64 * 72;         // 8 warps x 16.. (32 rows) x 68

    const int tid  = threadIdx.x;
    const int lane = tid & 31;
    const int wid  = tid >> 5;            // 0..7
    const int g    = lane >> 2;
    const int t    = lane & 3;
    const int b    = blockIdx.z;
    const int h    = blockIdx.y;
    const int q0   = blockIdx.x * 256;
    const int qr   = wid * 32;            // warp's q-row base within tile
    float* Pw = Ps + wid * 32 * 68;

    const uint32_t ksBase = (uint32_t)__cvta_generic_to_shared(Ks);
    const uint32_t vsBase = (uint32_t)__cvta_generic_to_shared(Vs);
    const uint32_t ksStage = (uint32_t)(sizeof(float) * 64 * 68);
    const uint32_t vsStage = (uint32_t)(sizeof(float) * 64 * 72);

    // Load Q tile (256 x 64), scale by 1/8, convert tf32
#pragma unroll
    for (int ii = 0; ii < 16; ii++) {
        int idx = tid + 256 * ii;
        int row = idx >> 4, c4 = (idx & 15) * 4;
        float4 v = *(const float4*)(Q + ((size_t)(b * SS + q0 + row) * DM + h * DH + c4));
        Qs[row * 68 + c4 + 0] = tf32r(v.x * 0.125f);
        Qs[row * 68 + c4 + 1] = tf32r(v.y * 0.125f);
        Qs[row * 68 + c4 + 2] = tf32r(v.z * 0.125f);
        Qs[row * 68 + c4 + 3] = tf32r(v.w * 0.125f);
    }

    // Issue K/V tile k0 into buffer buf (256 thr x 4 chunks each matrix)
    auto issue_kv = [&](int k0, int buf) {
#pragma unroll
        for (int ii = 0; ii < 4; ii++) {
            int idx = tid + 256 * ii;
            int row = idx >> 4, c4 = (idx & 15) * 4;
            size_t gb = (size_t)(b * SS + k0 + row) * DM + h * DH + c4;
            cp_async16(ksBase + buf * ksStage + (uint32_t)((row * 68 + c4) * 4), K + gb);
            cp_async16(vsBase + buf * vsStage + (uint32_t)((row * 72 + c4) * 4), V + gb);
        }
        cp_commit();
    };

    issue_kv(0, 0);

    float o[2][8][4];
#pragma unroll
    for (int mf = 0; mf < 2; mf++)
#pragma unroll
        for (int nf = 0; nf < 8; nf++)
#pragma unroll
            for (int i = 0; i < 4; i++) o[mf][nf][i] = 0.f;
    float mrow[4] = {-1e30f, -1e30f, -1e30f, -1e30f};
    float lrow[4] = {0.f, 0.f, 0.f, 0.f};

    int it = 0;
    for (int k0 = 0; k0 < SS; k0 += 64, it++) {
        cp_wait0();
        __syncthreads();
        const int cb = it & 1;
        if (k0 + 64 < SS) issue_kv(k0 + 64, cb ^ 1);

        const float* Kb = Ks + cb * 64 * 68;
        const float* Vb = Vs + cb * 64 * 72;

        // S = Q @ K^T (Q pre-scaled). s[mf][nf][4]
        float s[2][8][4];
#pragma unroll
        for (int mf = 0; mf < 2; mf++)
#pragma unroll
            for (int nf = 0; nf < 8; nf++)
#pragma unroll
                for (int i = 0; i < 4; i++) s[mf][nf][i] = 0.f;

#pragma unroll
        for (int kk = 0; kk < 8; kk++) {
            float a[2][4];
#pragma unroll
            for (int mf = 0; mf < 2; mf++) {
                const int r = qr + mf * 16;
                a[mf][0] = Qs[(r + g    ) * 68 + kk * 8 + t    ];
                a[mf][1] = Qs[(r + g + 8) * 68 + kk * 8 + t    ];
                a[mf][2] = Qs[(r + g    ) * 68 + kk * 8 + t + 4];
                a[mf][3] = Qs[(r + g + 8) * 68 + kk * 8 + t + 4];
            }
#pragma unroll
            for (int nf = 0; nf < 8; nf++) {
                float bfr[2];
                bfr[0] = tf32r(Kb[(nf * 8 + g) * 68 + kk * 8 + t    ]);
                bfr[1] = tf32r(Kb[(nf * 8 + g) * 68 + kk * 8 + t + 4]);
                mma8(s[0][nf], a[0], bfr);
                mma8(s[1][nf], a[1], bfr);
            }
        }

        // Online softmax per mf tile (rows qr+mf*16+g and +8)
#pragma unroll
        for (int mf = 0; mf < 2; mf++) {
            float mx0 = -1e30f, mx1 = -1e30f;
#pragma unroll
            for (int nf = 0; nf < 8; nf++) {
                mx0 = fmaxf(mx0, fmaxf(s[mf][nf][0], s[mf][nf][1]));
                mx1 = fmaxf(mx1, fmaxf(s[mf][nf][2], s[mf][nf][3]));
            }
            mx0 = fmaxf(mx0, __shfl_xor_sync(0xffffffffu, mx0, 1));
            mx0 = fmaxf(mx0, __shfl_xor_sync(0xffffffffu, mx0, 2));
            mx1 = fmaxf(mx1, __shfl_xor_sync(0xffffffffu, mx1, 1));
            mx1 = fmaxf(mx1, __shfl_xor_sync(0xffffffffu, mx1, 2));

            float mn0 = fmaxf(mrow[mf * 2    ], mx0);
            float mn1 = fmaxf(mrow[mf * 2 + 1], mx1);
            float cr0 = __expf(mrow[mf * 2    ] - mn0);
            float cr1 = __expf(mrow[mf * 2 + 1] - mn1);
            mrow[mf * 2] = mn0; mrow[mf * 2 + 1] = mn1;

            float sum0 = 0.f, sum1 = 0.f;
#pragma unroll
            for (int nf = 0; nf < 8; nf++) {
                s[mf][nf][0] = __expf(s[mf][nf][0] - mn0);
                s[mf][nf][1] = __expf(s[mf][nf][1] - mn0);
                s[mf][nf][2] = __expf(s[mf][nf][2] - mn1);
                s[mf][nf][3] = __expf(s[mf][nf][3] - mn1);
                sum0 += s[mf][nf][0] + s[mf][nf][1];
                sum1 += s[mf][nf][2] + s[mf][nf][3];
            }
            sum0 += __shfl_xor_sync(0xffffffffu, sum0, 1);
            sum0 += __shfl_xor_sync(0xffffffffu, sum0, 2);
            sum1 += __shfl_xor_sync(0xffffffffu, sum1, 1);
            sum1 += __shfl_xor_sync(0xffffffffu, sum1, 2);
            lrow[mf * 2]     = lrow[mf * 2]     * cr0 + sum0;
            lrow[mf * 2 + 1] = lrow[mf * 2 + 1] * cr1 + sum1;

#pragma unroll
            for (int nf = 0; nf < 8; nf++) {
                o[mf][nf][0] *= cr0; o[mf][nf][1] *= cr0;
                o[mf][nf][2] *= cr1; o[mf][nf][3] *= cr1;
                Pw[(mf * 16 + g    ) * 68 + nf * 8 + 2 * t    ] = tf32r(s[mf][nf][0]);
                Pw[(mf * 16 + g    ) * 68 + nf * 8 + 2 * t + 1] = tf32r(s[mf][nf][1]);
                Pw[(mf * 16 + g + 8) * 68 + nf * 8 + 2 * t    ] = tf32r(s[mf][nf][2]);
                Pw[(mf * 16 + g + 8) * 68 + nf * 8 + 2 * t + 1] = tf32r(s[mf][nf][3]);
            }
        }
        __syncwarp();

        // O += P @ V (V B-frags reused across both mf tiles)
#pragma unroll
        for (int kk = 0; kk < 8; kk++) {
            float a[2][4];
#pragma unroll
            for (int mf = 0; mf < 2; mf++) {
                const int r = mf * 16;
                a[mf][0] = Pw[(r + g    ) * 68 + kk * 8 + t    ];
                a[mf][1] = Pw[(r + g + 8) * 68 + kk * 8 + t    ];
                a[mf][2] = Pw[(r + g    ) * 68 + kk * 8 + t + 4];
                a[mf][3] = Pw[(r + g + 8) * 68 + kk * 8 + t + 4];
            }
#pragma unroll
            for (int nf = 0; nf < 8; nf++) {
                float bfr[2];
                bfr[0] = tf32r(Vb[(kk * 8 + t    ) * 72 + nf * 8 + g]);
                bfr[1] = tf32r(Vb[(kk * 8 + t + 4) * 72 + nf * 8 + g]);
                mma8(o[0][nf], a[0], bfr);
                mma8(o[1][nf], a[1], bfr);
            }
        }
        // next-iter P write guarded by the top-of-loop __syncthreads()
    }

    // Finalize, store context tokens
#pragma unroll
    for (int mf = 0; mf < 2; mf++) {
        const float inv0 = 1.f / lrow[mf * 2];
        const float inv1 = 1.f / lrow[mf * 2 + 1];
        const int row0 = b * SS + q0 + qr + mf * 16 + g;
#pragma unroll
        for (int nf = 0; nf < 8; nf++) {
            const int cc = h * DH + nf * 8 + 2 * t;
            *(float2*)(Ctx + (size_t)row0 * DM + cc) =
                make_float2(o[mf][nf][0] * inv0, o[mf][nf][1] * inv0);
            *(float2*)(Ctx + (size_t)(row0 + 8) * DM + cc) =
                make_float2(o[mf][nf][2] * inv1, o[mf][nf][3] * inv1);
        }
    }
}

// ---------------------------------------------------------------------------
// LayerNorm over last dim (768), one block per token row.
// ---------------------------------------------------------------------------
__global__ __launch_bounds__(256) void ln_kernel(
    const float* __restrict__ Hbuf, const float* __restrict__ gamma,
    const float* __restrict__ beta, float* __restrict__ out)
{
    __shared__ float red[16];
    const int row = blockIdx.x;
    const float* hp = Hbuf + (size_t)row * DM;

    float v[3];
    float sum = 0.f, sq = 0.f;
#pragma unroll
    for (int i = 0; i < 3; i++) {
        v[i] = hp[threadIdx.x + 256 * i];
        sum += v[i];
        sq  += v[i] * v[i];
    }
#pragma unroll
    for (int off = 16; off > 0; off >>= 1) {
        sum += __shfl_xor_sync(0xffffffffu, sum, off);
        sq  += __shfl_xor_sync(0xffffffffu, sq,  off);
    }
    const int wid = threadIdx.x >> 5, lane = threadIdx.x & 31;
    if (lane == 0) { red[wid] = sum; red[8 + wid] = sq; }
    __syncthreads();
    float ts = 0.f, tq = 0.f;
#pragma unroll
    for (int w = 0; w < 8; w++) { ts += red[w]; tq += red[8 + w]; }

    const float mean = ts * (1.f / (float)DM);
    const float var  = tq * (1.f / (float)DM) - mean * mean;
    const float rstd = rsqrtf(var + EPS);

#pragma unroll
    for (int i = 0; i < 3; i++) {
        int cIdx = threadIdx.x + 256 * i;
        out[(size_t)row * DM + cIdx] = (v[i] - mean) * rstd * gamma[cIdx] + beta[cIdx];
    }
}

// ---------------------------------------------------------------------------
// Launch
// ---------------------------------------------------------------------------
extern "C" void kernel_launch(void* const* d_in, const int* in_sizes, int n_in,
                              void* d_out, int out_size)
{
    const float* x     = (const float*)d_in[0];
    const float* Wq    = (const float*)d_in[1];
    const float* bq    = (const float*)d_in[2];
    const float* Wk    = (const float*)d_in[3];
    const float* bk    = (const float*)d_in[4];
    const float* Wv    = (const float*)d_in[5];
    const float* bv    = (const float*)d_in[6];
    const float* W1    = (const float*)d_in[7];
    const float* b1    = (const float*)d_in[8];
    const float* W2    = (const float*)d_in[9];
    const float* b2    = (const float*)d_in[10];
    const float* gamma = (const float*)d_in[11];
    const float* beta  = (const float*)d_in[12];
    float* out = (float*)d_out;

    void *pQ, *pK, *pV, *pCtx, *pHid, *pH;
    cudaGetSymbolAddress(&pQ,   g_Q);
    cudaGetSymbolAddress(&pK,   g_K);
    cudaGetSymbolAddress(&pV,   g_V);
    cudaGetSymbolAddress(&pCtx, g_Ctx);
    cudaGetSymbolAddress(&pHid, g_Hid);
    cudaGetSymbolAddress(&pH,   g_H);

    // attn smem: Qs 256*68 + Ks 2*64*68 + Vs 2*64*72 + Ps 8*32*68 floats
    const int smem_attn =
        (256 * 68 + 2 * 64 * 68 + 2 * 64 * 72 + 8 * 32 * 68) * (int)sizeof(float);
    cudaFuncSetAttribute(attn_tc, cudaFuncAttributeMaxDynamicSharedMemorySize,
                         smem_attn);

    dim3 blk(256);

    // QKV projections (tf32 tensor cores, cp.async pipeline)
    dim3 gQKV(DM / 128, NTOK / 128);  // (6, 64)
    gemm_tc<0><<<gQKV, blk>>>(x, Wq, bq, nullptr, (float*)pQ, NTOK, DM, DM);
    gemm_tc<0><<<gQKV, blk>>>(x, Wk, bk, nullptr, (float*)pK, NTOK, DM, DM);
    gemm_tc<0><<<gQKV, blk>>>(x, Wv, bv, nullptr, (float*)pV, NTOK, DM, DM);

    // Attention: q-tile 256 per CTA, 8 warps
    dim3 gAttn(SS / 256, HH, BB);     // (8, 12, 4)
    attn_tc<<<gAttn, dim3(256), smem_attn>>>((const float*)pQ, (const float*)pK,
                                             (const float*)pV, (float*)pCtx);

    // MLP
    dim3 gM1(2 * DM / 128, NTOK / 128);  // (12, 64)
    gemm_tc<1><<<gM1, blk>>>((const float*)pCtx, W1, b1, nullptr,
                             (float*)pHid, NTOK, 2 * DM, DM);
    dim3 gM2(DM / 128, NTOK / 128);      // (6, 64)
    gemm_tc<2><<<gM2, blk>>>((const float*)pHid, W2, b2, x,
                             (float*)pH, NTOK, DM, 2 * DM);

    // LayerNorm -> output
    ln_kernel<<<NTOK, blk>>>((const float*)pH, gamma, beta, out);
}

// round 14
// speedup vs baseline: 1.1061x; 1.1060x over previous
#include <cuda_runtime.h>
#include <cuda_bf16.h>
#include <math.h>
#include <stdint.h>

// Problem constants
static constexpr int BB   = 4;
static constexpr int SS   = 2048;
static constexpr int DM   = 768;
static constexpr int HH   = 12;
static constexpr int DH   = 64;
static constexpr int NTOK = BB * SS;          // 8192
static constexpr float EPS = 1e-5f;

// Scratch (device globals: no allocation)
__device__ float g_X  [NTOK * DM];            // tf32-rounded x
__device__ float g_Wq [DM * DM];
__device__ float g_Wk [DM * DM];
__device__ float g_Wv [DM * DM];
__device__ float g_W1 [DM * 2 * DM];
__device__ float g_W2 [2 * DM * DM];
__device__ float g_Q  [NTOK * DM];
__device__ float g_K  [NTOK * DM];
__device__ float g_V  [NTOK * DM];
__device__ float g_Ctx[NTOK * DM];
__device__ float g_Hid[NTOK * 2 * DM];
__device__ float g_H  [NTOK * DM];

// ---------------------------------------------------------------------------
// TF32 / cp.async helpers
// ---------------------------------------------------------------------------
__device__ __forceinline__ float tf32r(float x) {
    uint32_t u;
    asm("cvt.rna.tf32.f32 %0, %1;" : "=r"(u) : "f"(x));
    return __uint_as_float(u);
}

__device__ __forceinline__ void cp_async8(uint32_t dst, const void* src) {
    asm volatile("cp.async.ca.shared.global [%0], [%1], 8;\n" :: "r"(dst), "l"(src));
}
__device__ __forceinline__ void cp_async16(uint32_t dst, const void* src) {
    asm volatile("cp.async.cg.shared.global [%0], [%1], 16;\n" :: "r"(dst), "l"(src));
}
__device__ __forceinline__ void cp_commit() {
    asm volatile("cp.async.commit_group;\n" ::: "memory");
}
__device__ __forceinline__ void cp_wait0() {
    asm volatile("cp.async.wait_group 0;\n" ::: "memory");
}

// D(16x8) += A(16x8) * B(8x8)  tf32 inputs, fp32 accum.
__device__ __forceinline__ void mma8(float* c, const float* a, const float* b) {
    asm volatile(
        "mma.sync.aligned.m16n8k8.row.col.f32.tf32.tf32.f32 "
        "{%0,%1,%2,%3}, {%4,%5,%6,%7}, {%8,%9}, {%0,%1,%2,%3};\n"
        : "+f"(c[0]), "+f"(c[1]), "+f"(c[2]), "+f"(c[3])
        : "r"(__float_as_uint(a[0])), "r"(__float_as_uint(a[1])),
          "r"(__float_as_uint(a[2])), "r"(__float_as_uint(a[3])),
          "r"(__float_as_uint(b[0])), "r"(__float_as_uint(b[1])));
}

// ---------------------------------------------------------------------------
// Elementwise tf32-RNA pre-round (float4), exact-size launch.
// ---------------------------------------------------------------------------
__global__ __launch_bounds__(256) void round_kernel(const float* __restrict__ src,
                                                    float* __restrict__ dst)
{
    int i = (blockIdx.x * 256 + threadIdx.x) * 4;
    float4 v = *(const float4*)(src + i);
    v.x = tf32r(v.x); v.y = tf32r(v.y); v.z = tf32r(v.z); v.w = tf32r(v.w);
    *(float4*)(dst + i) = v;
}

// ---------------------------------------------------------------------------
// Shared GEMM mainloop (inputs pre-rounded to tf32; no cvt in loop).
// CTA 128x128, 8 warps (4x2), warp tile 32x64, BK=16, 2-stage cp.async.
// Accumulates into c[2][8][4].
// ---------------------------------------------------------------------------
struct SmemGemm {
    float As[2][128][20];
    float Bs[2][16][136];
};

__device__ __forceinline__ void gemm_mainloop(
    const float* __restrict__ A, const float* __restrict__ W,
    int m0, int n0, int N, int K, SmemGemm* smp, float c[2][8][4])
{
    const int tid  = threadIdx.x;
    const int lane = tid & 31;
    const int wid  = tid >> 5;
    const int g    = lane >> 2;
    const int t    = lane & 3;
    const int wm   = wid & 3;
    const int wn   = wid >> 2;

    uint32_t a_smem[4], b_smem[2];
    const float* a_gptr[4];
    const float* b_gptr[2];
#pragma unroll
    for (int j = 0; j < 4; j++) {
        int id = tid + 256 * j;
        int row = id >> 3, cp = id & 7;
        a_smem[j] = (uint32_t)__cvta_generic_to_shared(&smp->As[0][row][cp * 2]);
        a_gptr[j] = A + (size_t)(m0 + row) * K + cp * 2;
    }
#pragma unroll
    for (int j = 0; j < 2; j++) {
        int id = tid + 256 * j;
        int row = id >> 5, c4 = id & 31;
        b_smem[j] = (uint32_t)__cvta_generic_to_shared(&smp->Bs[0][row][c4 * 4]);
        b_gptr[j] = W + (size_t)row * N + n0 + c4 * 4;
    }
    const uint32_t aStage = (uint32_t)(sizeof(float) * 128 * 20);
    const uint32_t bStage = (uint32_t)(sizeof(float) * 16 * 136);

#pragma unroll
    for (int j = 0; j < 4; j++) cp_async8(a_smem[j], a_gptr[j]);
#pragma unroll
    for (int j = 0; j < 2; j++) cp_async16(b_smem[j], b_gptr[j]);
    cp_commit();

    const int nslab = K >> 4;
    for (int i = 0; i < nslab; i++) {
        cp_wait0();
        __syncthreads();

        const int cb = i & 1;
        if (i + 1 < nslab) {
            const int nb = (i + 1) & 1;
            const int kt = (i + 1) << 4;
#pragma unroll
            for (int j = 0; j < 4; j++)
                cp_async8(a_smem[j] + nb * aStage, a_gptr[j] + kt);
#pragma unroll
            for (int j = 0; j < 2; j++)
                cp_async16(b_smem[j] + nb * bStage, b_gptr[j] + (size_t)kt * N);
            cp_commit();
        }

#pragma unroll
        for (int kk = 0; kk < 2; kk++) {
            float a[2][4];
#pragma unroll
            for (int mf = 0; mf < 2; mf++) {
                const int r = wm * 32 + mf * 16;
                a[mf][0] = smp->As[cb][r + g    ][kk * 8 + t    ];
                a[mf][1] = smp->As[cb][r + g + 8][kk * 8 + t    ];
                a[mf][2] = smp->As[cb][r + g    ][kk * 8 + t + 4];
                a[mf][3] = smp->As[cb][r + g + 8][kk * 8 + t + 4];
            }
            float b[8][2];
#pragma unroll
            for (int nf = 0; nf < 8; nf++) {
                const int cc = wn * 64 + nf * 8 + g;
                b[nf][0] = smp->Bs[cb][kk * 8 + t    ][cc];
                b[nf][1] = smp->Bs[cb][kk * 8 + t + 4][cc];
            }
#pragma unroll
            for (int mf = 0; mf < 2; mf++)
#pragma unroll
                for (int nf = 0; nf < 8; nf++)
                    mma8(c[mf][nf], a[mf], b[nf]);
        }
    }
}

// ---------------------------------------------------------------------------
// Merged QKV GEMM: z = blockIdx.z selects {Wq->Q, Wk->K, Wv->V}.
// Epilogue: (acc + bias) * scale, tf32-rounded (Q scaled by 1/8).
// ---------------------------------------------------------------------------
__global__ __launch_bounds__(256, 2) void qkv_tc(
    const float* __restrict__ A,
    const float* __restrict__ W0, const float* __restrict__ W1p,
    const float* __restrict__ W2p,
    const float* __restrict__ b0, const float* __restrict__ b1p,
    const float* __restrict__ b2p,
    float* __restrict__ C0, float* __restrict__ C1p, float* __restrict__ C2p)
{
    __shared__ SmemGemm smem;
    const int z = blockIdx.z;
    const float* W = (z == 0) ? W0 : (z == 1) ? W1p : W2p;
    const float* bias = (z == 0) ? b0 : (z == 1) ? b1p : b2p;
    float* C = (z == 0) ? C0 : (z == 1) ? C1p : C2p;
    const float scale = (z == 0) ? 0.125f : 1.0f;

    const int m0 = blockIdx.y * 128;
    const int n0 = blockIdx.x * 128;

    float c[2][8][4];
#pragma unroll
    for (int mf = 0; mf < 2; mf++)
#pragma unroll
        for (int nf = 0; nf < 8; nf++)
#pragma unroll
            for (int i = 0; i < 4; i++) c[mf][nf][i] = 0.f;

    gemm_mainloop(A, W, m0, n0, DM, DM, &smem, c);

    const int lane = threadIdx.x & 31;
    const int wid  = threadIdx.x >> 5;
    const int g    = lane >> 2;
    const int t    = lane & 3;
    const int wm   = wid & 3;
    const int wn   = wid >> 2;
#pragma unroll
    for (int mf = 0; mf < 2; mf++) {
        const int r0 = m0 + wm * 32 + mf * 16 + g;
#pragma unroll
        for (int nf = 0; nf < 8; nf++) {
            const int cc = n0 + wn * 64 + nf * 8 + 2 * t;
            float2 bb = *(const float2*)(bias + cc);
            float v0 = tf32r((c[mf][nf][0] + bb.x) * scale);
            float v1 = tf32r((c[mf][nf][1] + bb.y) * scale);
            float v2 = tf32r((c[mf][nf][2] + bb.x) * scale);
            float v3 = tf32r((c[mf][nf][3] + bb.y) * scale);
            *(float2*)(C + (size_t)r0 * DM + cc)       = make_float2(v0, v1);
            *(float2*)(C + (size_t)(r0 + 8) * DM + cc) = make_float2(v2, v3);
        }
    }
}

// ---------------------------------------------------------------------------
// Generic GEMM for MLP. EPI = 1: bias+ReLU, tf32-rounded output;
//                        EPI = 2: bias+residual, raw fp32 output.
// ---------------------------------------------------------------------------
template <int EPI>
__global__ __launch_bounds__(256, 2) void gemm_tc(
    const float* __restrict__ A, const float* __restrict__ W,
    const float* __restrict__ bias, const float* __restrict__ res,
    float* __restrict__ C, int M, int N, int K)
{
    __shared__ SmemGemm smem;
    const int m0 = blockIdx.y * 128;
    const int n0 = blockIdx.x * 128;

    float c[2][8][4];
#pragma unroll
    for (int mf = 0; mf < 2; mf++)
#pragma unroll
        for (int nf = 0; nf < 8; nf++)
#pragma unroll
            for (int i = 0; i < 4; i++) c[mf][nf][i] = 0.f;

    gemm_mainloop(A, W, m0, n0, N, K, &smem, c);

    const int lane = threadIdx.x & 31;
    const int wid  = threadIdx.x >> 5;
    const int g    = lane >> 2;
    const int t    = lane & 3;
    const int wm   = wid & 3;
    const int wn   = wid >> 2;
#pragma unroll
    for (int mf = 0; mf < 2; mf++) {
        const int r0 = m0 + wm * 32 + mf * 16 + g;
#pragma unroll
        for (int nf = 0; nf < 8; nf++) {
            const int cc = n0 + wn * 64 + nf * 8 + 2 * t;
            float2 bb = *(const float2*)(bias + cc);
            float v0 = c[mf][nf][0] + bb.x;
            float v1 = c[mf][nf][1] + bb.y;
            float v2 = c[mf][nf][2] + bb.x;
            float v3 = c[mf][nf][3] + bb.y;
            if (EPI == 1) {
                v0 = tf32r(fmaxf(v0, 0.f)); v1 = tf32r(fmaxf(v1, 0.f));
                v2 = tf32r(fmaxf(v2, 0.f)); v3 = tf32r(fmaxf(v3, 0.f));
            }
            if (EPI == 2) {
                float2 r0v = *(const float2*)(res + (size_t)r0 * N + cc);
                float2 r1v = *(const float2*)(res + (size_t)(r0 + 8) * N + cc);
                v0 += r0v.x; v1 += r0v.y; v2 += r1v.x; v3 += r1v.y;
            }
            *(float2*)(C + (size_t)r0 * N + cc)       = make_float2(v0, v1);
            *(float2*)(C + (size_t)(r0 + 8) * N + cc) = make_float2(v2, v3);
        }
    }
}

// ---------------------------------------------------------------------------
// Flash attention with TF32 mma. One CTA per (b, h, 256-row q tile).
// 256 threads = 8 warps; each warp owns 32 q rows (2 mf tiles of 16).
// Q/K/V arrive pre-rounded (Q pre-scaled); no cvt in the mma loops.
// ---------------------------------------------------------------------------
__global__ __launch_bounds__(256, 1) void attn_tc(
    const float* __restrict__ Q, const float* __restrict__ K,
    const float* __restrict__ V, float* __restrict__ Ctx)
{
    extern __shared__ float sm[];
    float* Qs = sm;                       // 256 x 68
    float* Ks = Qs + 256 * 68;            // 2 x 64 x 68
    float* Vs = Ks + 2 * 64 * 68;         // 2 x 64 x 72
    float* Ps = Vs + 2 * 64 * 72;         // 8 warps x 32 x 68

    const int tid  = threadIdx.x;
    const int lane = tid & 31;
    const int wid  = tid >> 5;
    const int g    = lane >> 2;
    const int t    = lane & 3;
    const int b    = blockIdx.z;
    const int h    = blockIdx.y;
    const int q0   = blockIdx.x * 256;
    const int qr   = wid * 32;
    float* Pw = Ps + wid * 32 * 68;

    const uint32_t ksBase = (uint32_t)__cvta_generic_to_shared(Ks);
    const uint32_t vsBase = (uint32_t)__cvta_generic_to_shared(Vs);
    const uint32_t ksStage = (uint32_t)(sizeof(float) * 64 * 68);
    const uint32_t vsStage = (uint32_t)(sizeof(float) * 64 * 72);

    // Load Q tile (pre-scaled, pre-rounded): plain vector copy
#pragma unroll
    for (int ii = 0; ii < 16; ii++) {
        int idx = tid + 256 * ii;
        int row = idx >> 4, c4 = (idx & 15) * 4;
        float4 v = *(const float4*)(Q + ((size_t)(b * SS + q0 + row) * DM + h * DH + c4));
        *(float4*)&Qs[row * 68 + c4] = v;
    }

    auto issue_kv = [&](int k0, int buf) {
#pragma unroll
        for (int ii = 0; ii < 4; ii++) {
            int idx = tid + 256 * ii;
            int row = idx >> 4, c4 = (idx & 15) * 4;
            size_t gb = (size_t)(b * SS + k0 + row) * DM + h * DH + c4;
            cp_async16(ksBase + buf * ksStage + (uint32_t)((row * 68 + c4) * 4), K + gb);
            cp_async16(vsBase + buf * vsStage + (uint32_t)((row * 72 + c4) * 4), V + gb);
        }
        cp_commit();
    };

    issue_kv(0, 0);

    float o[2][8][4];
#pragma unroll
    for (int mf = 0; mf < 2; mf++)
#pragma unroll
        for (int nf = 0; nf < 8; nf++)
#pragma unroll
            for (int i = 0; i < 4; i++) o[mf][nf][i] = 0.f;
    float mrow[4] = {-1e30f, -1e30f, -1e30f, -1e30f};
    float lrow[4] = {0.f, 0.f, 0.f, 0.f};

    int it = 0;
    for (int k0 = 0; k0 < SS; k0 += 64, it++) {
        cp_wait0();
        __syncthreads();
        const int cb = it & 1;
        if (k0 + 64 < SS) issue_kv(k0 + 64, cb ^ 1);

        const float* Kb = Ks + cb * 64 * 68;
        const float* Vb = Vs + cb * 64 * 72;

        // S = Q @ K^T
        float s[2][8][4];
#pragma unroll
        for (int mf = 0; mf < 2; mf++)
#pragma unroll
            for (int nf = 0; nf < 8; nf++)
#pragma unroll
                for (int i = 0; i < 4; i++) s[mf][nf][i] = 0.f;

#pragma unroll
        for (int kk = 0; kk < 8; kk++) {
            float a[2][4];
#pragma unroll
            for (int mf = 0; mf < 2; mf++) {
                const int r = qr + mf * 16;
                a[mf][0] = Qs[(r + g    ) * 68 + kk * 8 + t    ];
                a[mf][1] = Qs[(r + g + 8) * 68 + kk * 8 + t    ];
                a[mf][2] = Qs[(r + g    ) * 68 + kk * 8 + t + 4];
                a[mf][3] = Qs[(r + g + 8) * 68 + kk * 8 + t + 4];
            }
#pragma unroll
            for (int nf = 0; nf < 8; nf++) {
                float bfr[2];
                bfr[0] = Kb[(nf * 8 + g) * 68 + kk * 8 + t    ];
                bfr[1] = Kb[(nf * 8 + g) * 68 + kk * 8 + t + 4];
                mma8(s[0][nf], a[0], bfr);
                mma8(s[1][nf], a[1], bfr);
            }
        }

        // Online softmax per mf tile
#pragma unroll
        for (int mf = 0; mf < 2; mf++) {
            float mx0 = -1e30f, mx1 = -1e30f;
#pragma unroll
            for (int nf = 0; nf < 8; nf++) {
                mx0 = fmaxf(mx0, fmaxf(s[mf][nf][0], s[mf][nf][1]));
                mx1 = fmaxf(mx1, fmaxf(s[mf][nf][2], s[mf][nf][3]));
            }
            mx0 = fmaxf(mx0, __shfl_xor_sync(0xffffffffu, mx0, 1));
            mx0 = fmaxf(mx0, __shfl_xor_sync(0xffffffffu, mx0, 2));
            mx1 = fmaxf(mx1, __shfl_xor_sync(0xffffffffu, mx1, 1));
            mx1 = fmaxf(mx1, __shfl_xor_sync(0xffffffffu, mx1, 2));

            float mn0 = fmaxf(mrow[mf * 2    ], mx0);
            float mn1 = fmaxf(mrow[mf * 2 + 1], mx1);
            float cr0 = __expf(mrow[mf * 2    ] - mn0);
            float cr1 = __expf(mrow[mf * 2 + 1] - mn1);
            mrow[mf * 2] = mn0; mrow[mf * 2 + 1] = mn1;

            float sum0 = 0.f, sum1 = 0.f;
#pragma unroll
            for (int nf = 0; nf < 8; nf++) {
                s[mf][nf][0] = __expf(s[mf][nf][0] - mn0);
                s[mf][nf][1] = __expf(s[mf][nf][1] - mn0);
                s[mf][nf][2] = __expf(s[mf][nf][2] - mn1);
                s[mf][nf][3] = __expf(s[mf][nf][3] - mn1);
                sum0 += s[mf][nf][0] + s[mf][nf][1];
                sum1 += s[mf][nf][2] + s[mf][nf][3];
            }
            sum0 += __shfl_xor_sync(0xffffffffu, sum0, 1);
            sum0 += __shfl_xor_sync(0xffffffffu, sum0, 2);
            sum1 += __shfl_xor_sync(0xffffffffu, sum1, 1);
            sum1 += __shfl_xor_sync(0xffffffffu, sum1, 2);
            lrow[mf * 2]     = lrow[mf * 2]     * cr0 + sum0;
            lrow[mf * 2 + 1] = lrow[mf * 2 + 1] * cr1 + sum1;

#pragma unroll
            for (int nf = 0; nf < 8; nf++) {
                o[mf][nf][0] *= cr0; o[mf][nf][1] *= cr0;
                o[mf][nf][2] *= cr1; o[mf][nf][3] *= cr1;
                Pw[(mf * 16 + g    ) * 68 + nf * 8 + 2 * t    ] = tf32r(s[mf][nf][0]);
                Pw[(mf * 16 + g    ) * 68 + nf * 8 + 2 * t + 1] = tf32r(s[mf][nf][1]);
                Pw[(mf * 16 + g + 8) * 68 + nf * 8 + 2 * t    ] = tf32r(s[mf][nf][2]);
                Pw[(mf * 16 + g + 8) * 68 + nf * 8 + 2 * t + 1] = tf32r(s[mf][nf][3]);
            }
        }
        __syncwarp();

        // O += P @ V
#pragma unroll
        for (int kk = 0; kk < 8; kk++) {
            float a[2][4];
#pragma unroll
            for (int mf = 0; mf < 2; mf++) {
                const int r = mf * 16;
                a[mf][0] = Pw[(r + g    ) * 68 + kk * 8 + t    ];
                a[mf][1] = Pw[(r + g + 8) * 68 + kk * 8 + t    ];
                a[mf][2] = Pw[(r + g    ) * 68 + kk * 8 + t + 4];
                a[mf][3] = Pw[(r + g + 8) * 68 + kk * 8 + t + 4];
            }
#pragma unroll
            for (int nf = 0; nf < 8; nf++) {
                float bfr[2];
                bfr[0] = Vb[(kk * 8 + t    ) * 72 + nf * 8 + g];
                bfr[1] = Vb[(kk * 8 + t + 4) * 72 + nf * 8 + g];
                mma8(o[0][nf], a[0], bfr);
                mma8(o[1][nf], a[1], bfr);
            }
        }
    }

    // Finalize, store context (tf32-rounded: feeds MLP1 A operand)
#pragma unroll
    for (int mf = 0; mf < 2; mf++) {
        const float inv0 = 1.f / lrow[mf * 2];
        const float inv1 = 1.f / lrow[mf * 2 + 1];
        const int row0 = b * SS + q0 + qr + mf * 16 + g;
#pragma unroll
        for (int nf = 0; nf < 8; nf++) {
            const int cc = h * DH + nf * 8 + 2 * t;
            *(float2*)(Ctx + (size_t)row0 * DM + cc) =
                make_float2(tf32r(o[mf][nf][0] * inv0), tf32r(o[mf][nf][1] * inv0));
            *(float2*)(Ctx + (size_t)(row0 + 8) * DM + cc) =
                make_float2(tf32r(o[mf][nf][2] * inv1), tf32r(o[mf][nf][3] * inv1));
        }
    }
}

// ---------------------------------------------------------------------------
// LayerNorm over last dim (768), one block per token row.
// ---------------------------------------------------------------------------
__global__ __launch_bounds__(256) void ln_kernel(
    const float* __restrict__ Hbuf, const float* __restrict__ gamma,
    const float* __restrict__ beta, float* __restrict__ out)
{
    __shared__ float red[16];
    const int row = blockIdx.x;
    const float* hp = Hbuf + (size_t)row * DM;

    float v[3];
    float sum = 0.f, sq = 0.f;
#pragma unroll
    for (int i = 0; i < 3; i++) {
        v[i] = hp[threadIdx.x + 256 * i];
        sum += v[i];
        sq  += v[i] * v[i];
    }
#pragma unroll
    for (int off = 16; off > 0; off >>= 1) {
        sum += __shfl_xor_sync(0xffffffffu, sum, off);
        sq  += __shfl_xor_sync(0xffffffffu, sq,  off);
    }
    const int wid = threadIdx.x >> 5, lane = threadIdx.x & 31;
    if (lane == 0) { red[wid] = sum; red[8 + wid] = sq; }
    __syncthreads();
    float ts = 0.f, tq = 0.f;
#pragma unroll
    for (int w = 0; w < 8; w++) { ts += red[w]; tq += red[8 + w]; }

    const float mean = ts * (1.f / (float)DM);
    const float var  = tq * (1.f / (float)DM) - mean * mean;
    const float rstd = rsqrtf(var + EPS);

#pragma unroll
    for (int i = 0; i < 3; i++) {
        int cIdx = threadIdx.x + 256 * i;
        out[(size_t)row * DM + cIdx] = (v[i] - mean) * rstd * gamma[cIdx] + beta[cIdx];
    }
}

// ---------------------------------------------------------------------------
// Launch
// ---------------------------------------------------------------------------
extern "C" void kernel_launch(void* const* d_in, const int* in_sizes, int n_in,
                              void* d_out, int out_size)
{
    const float* x     = (const float*)d_in[0];
    const float* Wq    = (const float*)d_in[1];
    const float* bq    = (const float*)d_in[2];
    const float* Wk    = (const float*)d_in[3];
    const float* bk    = (const float*)d_in[4];
    const float* Wv    = (const float*)d_in[5];
    const float* bv    = (const float*)d_in[6];
    const float* W1    = (const float*)d_in[7];
    const float* b1    = (const float*)d_in[8];
    const float* W2    = (const float*)d_in[9];
    const float* b2    = (const float*)d_in[10];
    const float* gamma = (const float*)d_in[11];
    const float* beta  = (const float*)d_in[12];
    float* out = (float*)d_out;

    void *pX, *pWq, *pWk, *pWv, *pW1, *pW2;
    void *pQ, *pK, *pV, *pCtx, *pHid, *pH;
    cudaGetSymbolAddress(&pX,   g_X);
    cudaGetSymbolAddress(&pWq,  g_Wq);
    cudaGetSymbolAddress(&pWk,  g_Wk);
    cudaGetSymbolAddress(&pWv,  g_Wv);
    cudaGetSymbolAddress(&pW1,  g_W1);
    cudaGetSymbolAddress(&pW2,  g_W2);
    cudaGetSymbolAddress(&pQ,   g_Q);
    cudaGetSymbolAddress(&pK,   g_K);
    cudaGetSymbolAddress(&pV,   g_V);
    cudaGetSymbolAddress(&pCtx, g_Ctx);
    cudaGetSymbolAddress(&pHid, g_Hid);
    cudaGetSymbolAddress(&pH,   g_H);

    const int smem_attn =
        (256 * 68 + 2 * 64 * 68 + 2 * 64 * 72 + 8 * 32 * 68) * (int)sizeof(float);
    cudaFuncSetAttribute(attn_tc, cudaFuncAttributeMaxDynamicSharedMemorySize,
                         smem_attn);

    dim3 blk(256);

    // Pre-round activations and weights to tf32 (RNA) once
    round_kernel<<<NTOK * DM / 1024, blk>>>(x,  (float*)pX);
    round_kernel<<<DM * DM / 1024, blk>>>(Wq, (float*)pWq);
    round_kernel<<<DM * DM / 1024, blk>>>(Wk, (float*)pWk);
    round_kernel<<<DM * DM / 1024, blk>>>(Wv, (float*)pWv);
    round_kernel<<<DM * 2 * DM / 1024, blk>>>(W1, (float*)pW1);
    round_kernel<<<2 * DM * DM / 1024, blk>>>(W2, (float*)pW2);

    // Merged QKV projections (z selects weight/output)
    dim3 gQKV(DM / 128, NTOK / 128, 3);  // (6, 64, 3)
    qkv_tc<<<gQKV, blk>>>((const float*)pX,
                          (const float*)pWq, (const float*)pWk, (const float*)pWv,
                          bq, bk, bv,
                          (float*)pQ, (float*)pK, (float*)pV);

    // Attention: q-tile 256 per CTA, 8 warps
    dim3 gAttn(SS / 256, HH, BB);     // (8, 12, 4)
    attn_tc<<<gAttn, dim3(256), smem_attn>>>((const float*)pQ, (const float*)pK,
                                             (const float*)pV, (float*)pCtx);

    // MLP
    dim3 gM1(2 * DM / 128, NTOK / 128);  // (12, 64)
    gemm_tc<1><<<gM1, blk>>>((const float*)pCtx, (const float*)pW1, b1, nullptr,
                             (float*)pHid, NTOK, 2 * DM, DM);
    dim3 gM2(DM / 128, NTOK / 128);      // (6, 64)
    gemm_tc<2><<<gM2, blk>>>((const float*)pHid, (const float*)pW2, b2, x,
                             (float*)pH, NTOK, DM, 2 * DM);

    // LayerNorm -> output
    ln_kernel<<<NTOK, blk>>>((const float*)pH, gamma, beta, out);
}

// round 15
// speedup vs baseline: 1.1551x; 1.0443x over previous
#include <cuda_runtime.h>
#include <cuda_bf16.h>
#include <math.h>
#include <stdint.h>

// Problem constants
static constexpr int BB   = 4;
static constexpr int SS   = 2048;
static constexpr int DM   = 768;
static constexpr int HH   = 12;
static constexpr int DH   = 64;
static constexpr int NTOK = BB * SS;          // 8192
static constexpr float EPS = 1e-5f;

// Scratch (device globals: no allocation)
__device__ float g_X  [NTOK * DM];            // tf32-rounded x
__device__ float g_Wq [DM * DM];
__device__ float g_Wk [DM * DM];
__device__ float g_Wv [DM * DM];
__device__ float g_W1 [DM * 2 * DM];
__device__ float g_W2 [2 * DM * DM];
__device__ float g_Q  [NTOK * DM];
__device__ float g_K  [NTOK * DM];
__device__ float g_V  [NTOK * DM];
__device__ float g_Ctx[NTOK * DM];
__device__ float g_Hid[NTOK * 2 * DM];
__device__ float g_H  [NTOK * DM];

// ---------------------------------------------------------------------------
// TF32 / cp.async helpers
// ---------------------------------------------------------------------------
__device__ __forceinline__ float tf32r(float x) {
    uint32_t u;
    asm("cvt.rna.tf32.f32 %0, %1;" : "=r"(u) : "f"(x));
    return __uint_as_float(u);
}

__device__ __forceinline__ void cp_async8(uint32_t dst, const void* src) {
    asm volatile("cp.async.ca.shared.global [%0], [%1], 8;\n" :: "r"(dst), "l"(src));
}
__device__ __forceinline__ void cp_async16(uint32_t dst, const void* src) {
    asm volatile("cp.async.cg.shared.global [%0], [%1], 16;\n" :: "r"(dst), "l"(src));
}
__device__ __forceinline__ void cp_commit() {
    asm volatile("cp.async.commit_group;\n" ::: "memory");
}
__device__ __forceinline__ void cp_wait0() {
    asm volatile("cp.async.wait_group 0;\n" ::: "memory");
}
__device__ __forceinline__ void cp_wait1() {
    asm volatile("cp.async.wait_group 1;\n" ::: "memory");
}

// D(16x8) += A(16x8) * B(8x8)  tf32 inputs, fp32 accum.
__device__ __forceinline__ void mma8(float* c, const float* a, const float* b) {
    asm volatile(
        "mma.sync.aligned.m16n8k8.row.col.f32.tf32.tf32.f32 "
        "{%0,%1,%2,%3}, {%4,%5,%6,%7}, {%8,%9}, {%0,%1,%2,%3};\n"
        : "+f"(c[0]), "+f"(c[1]), "+f"(c[2]), "+f"(c[3])
        : "r"(__float_as_uint(a[0])), "r"(__float_as_uint(a[1])),
          "r"(__float_as_uint(a[2])), "r"(__float_as_uint(a[3])),
          "r"(__float_as_uint(b[0])), "r"(__float_as_uint(b[1])));
}

// ---------------------------------------------------------------------------
// Elementwise tf32-RNA pre-round (float4), exact-size launch.
// ---------------------------------------------------------------------------
__global__ __launch_bounds__(256) void round_kernel(const float* __restrict__ src,
                                                    float* __restrict__ dst)
{
    int i = (blockIdx.x * 256 + threadIdx.x) * 4;
    float4 v = *(const float4*)(src + i);
    v.x = tf32r(v.x); v.y = tf32r(v.y); v.z = tf32r(v.z); v.w = tf32r(v.w);
    *(float4*)(dst + i) = v;
}

// ---------------------------------------------------------------------------
// Shared GEMM mainloop, 3-stage cp.async pipeline (wait_group 1).
// CTA 128x128, 8 warps (4x2), warp tile 32x64, BK=16.
// Inputs pre-rounded to tf32; no cvt in loop. Accumulates into c[2][8][4].
// ---------------------------------------------------------------------------
struct SmemGemm {
    float As[3][128][20];
    float Bs[3][16][136];
};

__device__ __forceinline__ void gemm_mainloop(
    const float* __restrict__ A, const float* __restrict__ W,
    int m0, int n0, int N, int K, SmemGemm* smp, float c[2][8][4])
{
    const int tid  = threadIdx.x;
    const int lane = tid & 31;
    const int wid  = tid >> 5;
    const int g    = lane >> 2;
    const int t    = lane & 3;
    const int wm   = wid & 3;
    const int wn   = wid >> 2;

    uint32_t a_smem[4], b_smem[2];
    const float* a_gptr[4];
    const float* b_gptr[2];
#pragma unroll
    for (int j = 0; j < 4; j++) {
        int id = tid + 256 * j;
        int row = id >> 3, cp = id & 7;
        a_smem[j] = (uint32_t)__cvta_generic_to_shared(&smp->As[0][row][cp * 2]);
        a_gptr[j] = A + (size_t)(m0 + row) * K + cp * 2;
    }
#pragma unroll
    for (int j = 0; j < 2; j++) {
        int id = tid + 256 * j;
        int row = id >> 5, c4 = id & 31;
        b_smem[j] = (uint32_t)__cvta_generic_to_shared(&smp->Bs[0][row][c4 * 4]);
        b_gptr[j] = W + (size_t)row * N + n0 + c4 * 4;
    }
    const uint32_t aStage = (uint32_t)(sizeof(float) * 128 * 20);
    const uint32_t bStage = (uint32_t)(sizeof(float) * 16 * 136);

    auto issue_slab = [&](int slab, int buf) {
        const int kt = slab << 4;
#pragma unroll
        for (int j = 0; j < 4; j++)
            cp_async8(a_smem[j] + buf * aStage, a_gptr[j] + kt);
#pragma unroll
        for (int j = 0; j < 2; j++)
            cp_async16(b_smem[j] + buf * bStage, b_gptr[j] + (size_t)kt * N);
        cp_commit();
    };

    const int nslab = K >> 4;
    // Prologue: slabs 0 and 1 in flight
    issue_slab(0, 0);
    issue_slab(1, 1);

    int buf = 0;
    for (int i = 0; i < nslab; i++) {
        cp_wait1();                 // slab i resident; slab i+1 may still fly
        __syncthreads();
        if (i + 2 < nslab) issue_slab(i + 2, (buf + 2) % 3);

        const int cb = buf;
#pragma unroll
        for (int kk = 0; kk < 2; kk++) {
            float a[2][4];
#pragma unroll
            for (int mf = 0; mf < 2; mf++) {
                const int r = wm * 32 + mf * 16;
                a[mf][0] = smp->As[cb][r + g    ][kk * 8 + t    ];
                a[mf][1] = smp->As[cb][r + g + 8][kk * 8 + t    ];
                a[mf][2] = smp->As[cb][r + g    ][kk * 8 + t + 4];
                a[mf][3] = smp->As[cb][r + g + 8][kk * 8 + t + 4];
            }
            float b[8][2];
#pragma unroll
            for (int nf = 0; nf < 8; nf++) {
                const int cc = wn * 64 + nf * 8 + g;
                b[nf][0] = smp->Bs[cb][kk * 8 + t    ][cc];
                b[nf][1] = smp->Bs[cb][kk * 8 + t + 4][cc];
            }
#pragma unroll
            for (int mf = 0; mf < 2; mf++)
#pragma unroll
                for (int nf = 0; nf < 8; nf++)
                    mma8(c[mf][nf], a[mf], b[nf]);
        }
        buf = (buf + 1) % 3;
    }
}

// ---------------------------------------------------------------------------
// Merged QKV GEMM: z = blockIdx.z selects {Wq->Q, Wk->K, Wv->V}.
// Epilogue: (acc + bias) * scale, tf32-rounded (Q scaled by 1/8).
// ---------------------------------------------------------------------------
__global__ __launch_bounds__(256, 2) void qkv_tc(
    const float* __restrict__ A,
    const float* __restrict__ W0, const float* __restrict__ W1p,
    const float* __restrict__ W2p,
    const float* __restrict__ b0, const float* __restrict__ b1p,
    const float* __restrict__ b2p,
    float* __restrict__ C0, float* __restrict__ C1p, float* __restrict__ C2p)
{
    __shared__ SmemGemm smem;
    const int z = blockIdx.z;
    const float* W = (z == 0) ? W0 : (z == 1) ? W1p : W2p;
    const float* bias = (z == 0) ? b0 : (z == 1) ? b1p : b2p;
    float* C = (z == 0) ? C0 : (z == 1) ? C1p : C2p;
    const float scale = (z == 0) ? 0.125f : 1.0f;

    const int m0 = blockIdx.y * 128;
    const int n0 = blockIdx.x * 128;

    float c[2][8][4];
#pragma unroll
    for (int mf = 0; mf < 2; mf++)
#pragma unroll
        for (int nf = 0; nf < 8; nf++)
#pragma unroll
            for (int i = 0; i < 4; i++) c[mf][nf][i] = 0.f;

    gemm_mainloop(A, W, m0, n0, DM, DM, &smem, c);

    const int lane = threadIdx.x & 31;
    const int wid  = threadIdx.x >> 5;
    const int g    = lane >> 2;
    const int t    = lane & 3;
    const int wm   = wid & 3;
    const int wn   = wid >> 2;
#pragma unroll
    for (int mf = 0; mf < 2; mf++) {
        const int r0 = m0 + wm * 32 + mf * 16 + g;
#pragma unroll
        for (int nf = 0; nf < 8; nf++) {
            const int cc = n0 + wn * 64 + nf * 8 + 2 * t;
            float2 bb = *(const float2*)(bias + cc);
            float v0 = tf32r((c[mf][nf][0] + bb.x) * scale);
            float v1 = tf32r((c[mf][nf][1] + bb.y) * scale);
            float v2 = tf32r((c[mf][nf][2] + bb.x) * scale);
            float v3 = tf32r((c[mf][nf][3] + bb.y) * scale);
            *(float2*)(C + (size_t)r0 * DM + cc)       = make_float2(v0, v1);
            *(float2*)(C + (size_t)(r0 + 8) * DM + cc) = make_float2(v2, v3);
        }
    }
}

// ---------------------------------------------------------------------------
// Generic GEMM for MLP. EPI = 1: bias+ReLU, tf32-rounded output;
//                        EPI = 2: bias+residual, raw fp32 output.
// ---------------------------------------------------------------------------
template <int EPI>
__global__ __launch_bounds__(256, 2) void gemm_tc(
    const float* __restrict__ A, const float* __restrict__ W,
    const float* __restrict__ bias, const float* __restrict__ res,
    float* __restrict__ C, int M, int N, int K)
{
    __shared__ SmemGemm smem;
    const int m0 = blockIdx.y * 128;
    const int n0 = blockIdx.x * 128;

    float c[2][8][4];
#pragma unroll
    for (int mf = 0; mf < 2; mf++)
#pragma unroll
        for (int nf = 0; nf < 8; nf++)
#pragma unroll
            for (int i = 0; i < 4; i++) c[mf][nf][i] = 0.f;

    gemm_mainloop(A, W, m0, n0, N, K, &smem, c);

    const int lane = threadIdx.x & 31;
    const int wid  = threadIdx.x >> 5;
    const int g    = lane >> 2;
    const int t    = lane & 3;
    const int wm   = wid & 3;
    const int wn   = wid >> 2;
#pragma unroll
    for (int mf = 0; mf < 2; mf++) {
        const int r0 = m0 + wm * 32 + mf * 16 + g;
#pragma unroll
        for (int nf = 0; nf < 8; nf++) {
            const int cc = n0 + wn * 64 + nf * 8 + 2 * t;
            float2 bb = *(const float2*)(bias + cc);
            float v0 = c[mf][nf][0] + bb.x;
            float v1 = c[mf][nf][1] + bb.y;
            float v2 = c[mf][nf][2] + bb.x;
            float v3 = c[mf][nf][3] + bb.y;
            if (EPI == 1) {
                v0 = tf32r(fmaxf(v0, 0.f)); v1 = tf32r(fmaxf(v1, 0.f));
                v2 = tf32r(fmaxf(v2, 0.f)); v3 = tf32r(fmaxf(v3, 0.f));
            }
            if (EPI == 2) {
                float2 r0v = *(const float2*)(res + (size_t)r0 * N + cc);
                float2 r1v = *(const float2*)(res + (size_t)(r0 + 8) * N + cc);
                v0 += r0v.x; v1 += r0v.y; v2 += r1v.x; v3 += r1v.y;
            }
            *(float2*)(C + (size_t)r0 * N + cc)       = make_float2(v0, v1);
            *(float2*)(C + (size_t)(r0 + 8) * N + cc) = make_float2(v2, v3);
        }
    }
}

// ---------------------------------------------------------------------------
// Flash attention, TF32 mma. One CTA per (b, h, 128-row q tile).
// 128 threads = 4 warps; warp owns 32 q rows (2 mf tiles of 16).
// Q fragments live in registers (extracted once from a staging buffer that is
// then re-used as the P buffer). K/V double-buffered via cp.async.
// smem = 106.5 KB -> 2 CTAs/SM for cross-CTA latency/barrier overlap.
// ---------------------------------------------------------------------------
__global__ __launch_bounds__(128, 2) void attn_tc(
    const float* __restrict__ Q, const float* __restrict__ K,
    const float* __restrict__ V, float* __restrict__ Ctx)
{
    extern __shared__ float sm[];
    float* Qs = sm;                       // 128 x 68 staging; later aliased as Ps
    float* Ps = sm;                       // 4 warps x 32 x 68 (same 8704 floats)
    float* Ks = sm + 128 * 68;            // 2 x 64 x 68
    float* Vs = Ks + 2 * 64 * 68;         // 2 x 64 x 72

    const int tid  = threadIdx.x;
    const int lane = tid & 31;
    const int wid  = tid >> 5;            // 0..3
    const int g    = lane >> 2;
    const int t    = lane & 3;
    const int b    = blockIdx.z;
    const int h    = blockIdx.y;
    const int q0   = blockIdx.x * 128;
    const int qr   = wid * 32;
    float* Pw = Ps + wid * 32 * 68;

    const uint32_t ksBase = (uint32_t)__cvta_generic_to_shared(Ks);
    const uint32_t vsBase = (uint32_t)__cvta_generic_to_shared(Vs);
    const uint32_t ksStage = (uint32_t)(sizeof(float) * 64 * 68);
    const uint32_t vsStage = (uint32_t)(sizeof(float) * 64 * 72);

    // Issue K/V tile k0 into buffer buf (128 thr x 8 chunks each matrix)
    auto issue_kv = [&](int k0, int buf) {
#pragma unroll
        for (int ii = 0; ii < 8; ii++) {
            int idx = tid + 128 * ii;
            int row = idx >> 4, c4 = (idx & 15) * 4;
            size_t gb = (size_t)(b * SS + k0 + row) * DM + h * DH + c4;
            cp_async16(ksBase + buf * ksStage + (uint32_t)((row * 68 + c4) * 4), K + gb);
            cp_async16(vsBase + buf * vsStage + (uint32_t)((row * 72 + c4) * 4), V + gb);
        }
        cp_commit();
    };

    issue_kv(0, 0);

    // Stage Q tile (128 x 64; pre-scaled, pre-rounded), then extract A-frags.
#pragma unroll
    for (int ii = 0; ii < 16; ii++) {
        int idx = tid + 128 * ii;
        int row = idx >> 4, c4 = (idx & 15) * 4;
        float4 v = *(const float4*)(Q + ((size_t)(b * SS + q0 + row) * DM + h * DH + c4));
        *(float4*)&Qs[row * 68 + c4] = v;
    }
    __syncthreads();

    float Qf[8][2][4];
#pragma unroll
    for (int kk = 0; kk < 8; kk++)
#pragma unroll
        for (int mf = 0; mf < 2; mf++) {
            const int r = qr + mf * 16;
            Qf[kk][mf][0] = Qs[(r + g    ) * 68 + kk * 8 + t    ];
            Qf[kk][mf][1] = Qs[(r + g + 8) * 68 + kk * 8 + t    ];
            Qf[kk][mf][2] = Qs[(r + g    ) * 68 + kk * 8 + t + 4];
            Qf[kk][mf][3] = Qs[(r + g + 8) * 68 + kk * 8 + t + 4];
        }
    __syncthreads();   // Qs dead; region becomes Ps

    float o[2][8][4];
#pragma unroll
    for (int mf = 0; mf < 2; mf++)
#pragma unroll
        for (int nf = 0; nf < 8; nf++)
#pragma unroll
            for (int i = 0; i < 4; i++) o[mf][nf][i] = 0.f;
    float mrow[4] = {-1e30f, -1e30f, -1e30f, -1e30f};
    float lrow[4] = {0.f, 0.f, 0.f, 0.f};

    int it = 0;
    for (int k0 = 0; k0 < SS; k0 += 64, it++) {
        cp_wait0();
        __syncthreads();
        const int cb = it & 1;
        if (k0 + 64 < SS) issue_kv(k0 + 64, cb ^ 1);

        const float* Kb = Ks + cb * 64 * 68;
        const float* Vb = Vs + cb * 64 * 72;

        // S = Q @ K^T (Q pre-scaled, frags in registers)
        float s[2][8][4];
#pragma unroll
        for (int mf = 0; mf < 2; mf++)
#pragma unroll
            for (int nf = 0; nf < 8; nf++)
#pragma unroll
                for (int i = 0; i < 4; i++) s[mf][nf][i] = 0.f;

#pragma unroll
        for (int kk = 0; kk < 8; kk++) {
#pragma unroll
            for (int nf = 0; nf < 8; nf++) {
                float bfr[2];
                bfr[0] = Kb[(nf * 8 + g) * 68 + kk * 8 + t    ];
                bfr[1] = Kb[(nf * 8 + g) * 68 + kk * 8 + t + 4];
                mma8(s[0][nf], Qf[kk][0], bfr);
                mma8(s[1][nf], Qf[kk][1], bfr);
            }
        }

        // Online softmax per mf tile (rows qr+mf*16+g and +8)
#pragma unroll
        for (int mf = 0; mf < 2; mf++) {
            float mx0 = -1e30f, mx1 = -1e30f;
#pragma unroll
            for (int nf = 0; nf < 8; nf++) {
                mx0 = fmaxf(mx0, fmaxf(s[mf][nf][0], s[mf][nf][1]));
                mx1 = fmaxf(mx1, fmaxf(s[mf][nf][2], s[mf][nf][3]));
            }
            mx0 = fmaxf(mx0, __shfl_xor_sync(0xffffffffu, mx0, 1));
            mx0 = fmaxf(mx0, __shfl_xor_sync(0xffffffffu, mx0, 2));
            mx1 = fmaxf(mx1, __shfl_xor_sync(0xffffffffu, mx1, 1));
            mx1 = fmaxf(mx1, __shfl_xor_sync(0xffffffffu, mx1, 2));

            float mn0 = fmaxf(mrow[mf * 2    ], mx0);
            float mn1 = fmaxf(mrow[mf * 2 + 1], mx1);
            float cr0 = __expf(mrow[mf * 2    ] - mn0);
            float cr1 = __expf(mrow[mf * 2 + 1] - mn1);
            mrow[mf * 2] = mn0; mrow[mf * 2 + 1] = mn1;

            float sum0 = 0.f, sum1 = 0.f;
#pragma unroll
            for (int nf = 0; nf < 8; nf++) {
                s[mf][nf][0] = __expf(s[mf][nf][0] - mn0);
                s[mf][nf][1] = __expf(s[mf][nf][1] - mn0);
                s[mf][nf][2] = __expf(s[mf][nf][2] - mn1);
                s[mf][nf][3] = __expf(s[mf][nf][3] - mn1);
                sum0 += s[mf][nf][0] + s[mf][nf][1];
                sum1 += s[mf][nf][2] + s[mf][nf][3];
            }
            sum0 += __shfl_xor_sync(0xffffffffu, sum0, 1);
            sum0 += __shfl_xor_sync(0xffffffffu, sum0, 2);
            sum1 += __shfl_xor_sync(0xffffffffu, sum1, 1);
            sum1 += __shfl_xor_sync(0xffffffffu, sum1, 2);
            lrow[mf * 2]     = lrow[mf * 2]     * cr0 + sum0;
            lrow[mf * 2 + 1] = lrow[mf * 2 + 1] * cr1 + sum1;

#pragma unroll
            for (int nf = 0; nf < 8; nf++) {
                o[mf][nf][0] *= cr0; o[mf][nf][1] *= cr0;
                o[mf][nf][2] *= cr1; o[mf][nf][3] *= cr1;
                Pw[(mf * 16 + g    ) * 68 + nf * 8 + 2 * t    ] = tf32r(s[mf][nf][0]);
                Pw[(mf * 16 + g    ) * 68 + nf * 8 + 2 * t + 1] = tf32r(s[mf][nf][1]);
                Pw[(mf * 16 + g + 8) * 68 + nf * 8 + 2 * t    ] = tf32r(s[mf][nf][2]);
                Pw[(mf * 16 + g + 8) * 68 + nf * 8 + 2 * t + 1] = tf32r(s[mf][nf][3]);
            }
        }
        __syncwarp();

        // O += P @ V (V B-frags reused across both mf tiles)
#pragma unroll
        for (int kk = 0; kk < 8; kk++) {
            float a[2][4];
#pragma unroll
            for (int mf = 0; mf < 2; mf++) {
                const int r = mf * 16;
                a[mf][0] = Pw[(r + g    ) * 68 + kk * 8 + t    ];
                a[mf][1] = Pw[(r + g + 8) * 68 + kk * 8 + t    ];
                a[mf][2] = Pw[(r + g    ) * 68 + kk * 8 + t + 4];
                a[mf][3] = Pw[(r + g + 8) * 68 + kk * 8 + t + 4];
            }
#pragma unroll
            for (int nf = 0; nf < 8; nf++) {
                float bfr[2];
                bfr[0] = Vb[(kk * 8 + t    ) * 72 + nf * 8 + g];
                bfr[1] = Vb[(kk * 8 + t + 4) * 72 + nf * 8 + g];
                mma8(o[0][nf], a[0], bfr);
                mma8(o[1][nf], a[1], bfr);
            }
        }
        // next-iter P write guarded by the top-of-loop __syncthreads()
    }

    // Finalize, store context (tf32-rounded: feeds MLP1 A operand)
#pragma unroll
    for (int mf = 0; mf < 2; mf++) {
        const float inv0 = 1.f / lrow[mf * 2];
        const float inv1 = 1.f / lrow[mf * 2 + 1];
        const int row0 = b * SS + q0 + qr + mf * 16 + g;
#pragma unroll
        for (int nf = 0; nf < 8; nf++) {
            const int cc = h * DH + nf * 8 + 2 * t;
            *(float2*)(Ctx + (size_t)row0 * DM + cc) =
                make_float2(tf32r(o[mf][nf][0] * inv0), tf32r(o[mf][nf][1] * inv0));
            *(float2*)(Ctx + (size_t)(row0 + 8) * DM + cc) =
                make_float2(tf32r(o[mf][nf][2] * inv1), tf32r(o[mf][nf][3] * inv1));
        }
    }
}

// ---------------------------------------------------------------------------
// LayerNorm over last dim (768), one block per token row.
// ---------------------------------------------------------------------------
__global__ __launch_bounds__(256) void ln_kernel(
    const float* __restrict__ Hbuf, const float* __restrict__ gamma,
    const float* __restrict__ beta, float* __restrict__ out)
{
    __shared__ float red[16];
    const int row = blockIdx.x;
    const float* hp = Hbuf + (size_t)row * DM;

    float v[3];
    float sum = 0.f, sq = 0.f;
#pragma unroll
    for (int i = 0; i < 3; i++) {
        v[i] = hp[threadIdx.x + 256 * i];
        sum += v[i];
        sq  += v[i] * v[i];
    }
#pragma unroll
    for (int off = 16; off > 0; off >>= 1) {
        sum += __shfl_xor_sync(0xffffffffu, sum, off);
        sq  += __shfl_xor_sync(0xffffffffu, sq,  off);
    }
    const int wid = threadIdx.x >> 5, lane = threadIdx.x & 31;
    if (lane == 0) { red[wid] = sum; red[8 + wid] = sq; }
    __syncthreads();
    float ts = 0.f, tq = 0.f;
#pragma unroll
    for (int w = 0; w < 8; w++) { ts += red[w]; tq += red[8 + w]; }

    const float mean = ts * (1.f / (float)DM);
    const float var  = tq * (1.f / (float)DM) - mean * mean;
    const float rstd = rsqrtf(var + EPS);

#pragma unroll
    for (int i = 0; i < 3; i++) {
        int cIdx = threadIdx.x + 256 * i;
        out[(size_t)row * DM + cIdx] = (v[i] - mean) * rstd * gamma[cIdx] + beta[cIdx];
    }
}

// ---------------------------------------------------------------------------
// Launch
// ---------------------------------------------------------------------------
extern "C" void kernel_launch(void* const* d_in, const int* in_sizes, int n_in,
                              void* d_out, int out_size)
{
    const float* x     = (const float*)d_in[0];
    const float* Wq    = (const float*)d_in[1];
    const float* bq    = (const float*)d_in[2];
    const float* Wk    = (const float*)d_in[3];
    const float* bk    = (const float*)d_in[4];
    const float* Wv    = (const float*)d_in[5];
    const float* bv    = (const float*)d_in[6];
    const float* W1    = (const float*)d_in[7];
    const float* b1    = (const float*)d_in[8];
    const float* W2    = (const float*)d_in[9];
    const float* b2    = (const float*)d_in[10];
    const float* gamma = (const float*)d_in[11];
    const float* beta  = (const float*)d_in[12];
    float* out = (float*)d_out;

    void *pX, *pWq, *pWk, *pWv, *pW1, *pW2;
    void *pQ, *pK, *pV, *pCtx, *pHid, *pH;
    cudaGetSymbolAddress(&pX,   g_X);
    cudaGetSymbolAddress(&pWq,  g_Wq);
    cudaGetSymbolAddress(&pWk,  g_Wk);
    cudaGetSymbolAddress(&pWv,  g_Wv);
    cudaGetSymbolAddress(&pW1,  g_W1);
    cudaGetSymbolAddress(&pW2,  g_W2);
    cudaGetSymbolAddress(&pQ,   g_Q);
    cudaGetSymbolAddress(&pK,   g_K);
    cudaGetSymbolAddress(&pV,   g_V);
    cudaGetSymbolAddress(&pCtx, g_Ctx);
    cudaGetSymbolAddress(&pHid, g_Hid);
    cudaGetSymbolAddress(&pH,   g_H);

    // attn smem: Qs/Ps alias 128*68 + Ks 2*64*68 + Vs 2*64*72 floats = 106496 B
    const int smem_attn =
        (128 * 68 + 2 * 64 * 68 + 2 * 64 * 72) * (int)sizeof(float);
    cudaFuncSetAttribute(attn_tc, cudaFuncAttributeMaxDynamicSharedMemorySize,
                         smem_attn);

    dim3 blk(256);

    // Pre-round activations and weights to tf32 (RNA) once
    round_kernel<<<NTOK * DM / 1024, blk>>>(x,  (float*)pX);
    round_kernel<<<DM * DM / 1024, blk>>>(Wq, (float*)pWq);
    round_kernel<<<DM * DM / 1024, blk>>>(Wk, (float*)pWk);
    round_kernel<<<DM * DM / 1024, blk>>>(Wv, (float*)pWv);
    round_kernel<<<DM * 2 * DM / 1024, blk>>>(W1, (float*)pW1);
    round_kernel<<<2 * DM * DM / 1024, blk>>>(W2, (float*)pW2);

    // Merged QKV projections (z selects weight/output)
    dim3 gQKV(DM / 128, NTOK / 128, 3);  // (6, 64, 3)
    qkv_tc<<<gQKV, blk>>>((const float*)pX,
                          (const float*)pWq, (const float*)pWk, (const float*)pWv,
                          bq, bk, bv,
                          (float*)pQ, (float*)pK, (float*)pV);

    // Attention: q-tile 128 per CTA, 4 warps, 2 CTAs/SM
    dim3 gAttn(SS / 128, HH, BB);     // (16, 12, 4)
    attn_tc<<<gAttn, dim3(128), smem_attn>>>((const float*)pQ, (const float*)pK,
                                             (const float*)pV, (float*)pCtx);

    // MLP
    dim3 gM1(2 * DM / 128, NTOK / 128);  // (12, 64)
    gemm_tc<1><<<gM1, blk>>>((const float*)pCtx, (const float*)pW1, b1, nullptr,
                             (float*)pHid, NTOK, 2 * DM, DM);
    dim3 gM2(DM / 128, NTOK / 128);      // (6, 64)
    gemm_tc<2><<<gM2, blk>>>((const float*)pHid, (const float*)pW2, b2, x,
                             (float*)pH, NTOK, DM, 2 * DM);

    // LayerNorm -> output
    ln_kernel<<<NTOK, blk>>>((const float*)pH, gamma, beta, out);
}

// round 16
// speedup vs baseline: 1.2670x; 1.0968x over previous
#include <cuda_runtime.h>
#include <cuda_bf16.h>
#include <math.h>
#include <stdint.h>

// Problem constants
static constexpr int BB   = 4;
static constexpr int SS   = 2048;
static constexpr int DM   = 768;
static constexpr int HH   = 12;
static constexpr int DH   = 64;
static constexpr int NTOK = BB * SS;          // 8192
static constexpr float EPS = 1e-5f;
static constexpr float LOG2E = 1.4426950408889634f;

// Scratch (device globals: no allocation)
__device__ float g_X  [NTOK * DM];            // tf32-rounded x
__device__ float g_Wq [DM * DM];
__device__ float g_Wk [DM * DM];
__device__ float g_Wv [DM * DM];
__device__ float g_W1 [DM * 2 * DM];
__device__ float g_W2 [2 * DM * DM];
__device__ float g_Q  [NTOK * DM];
__device__ float g_K  [NTOK * DM];
__device__ float g_V  [NTOK * DM];
__device__ float g_Ctx[NTOK * DM];
__device__ float g_Hid[NTOK * 2 * DM];
__device__ float g_H  [NTOK * DM];

// ---------------------------------------------------------------------------
// TF32 / cp.async helpers
// ---------------------------------------------------------------------------
__device__ __forceinline__ float tf32r(float x) {
    uint32_t u;
    asm("cvt.rna.tf32.f32 %0, %1;" : "=r"(u) : "f"(x));
    return __uint_as_float(u);
}

__device__ __forceinline__ void cp_async16(uint32_t dst, const void* src) {
    asm volatile("cp.async.cg.shared.global [%0], [%1], 16;\n" :: "r"(dst), "l"(src));
}
__device__ __forceinline__ void cp_commit() {
    asm volatile("cp.async.commit_group;\n" ::: "memory");
}
__device__ __forceinline__ void cp_wait0() {
    asm volatile("cp.async.wait_group 0;\n" ::: "memory");
}

// D(16x8) += A(16x8) * B(8x8)  tf32 inputs, fp32 accum.
__device__ __forceinline__ void mma8(float* c, const float* a, const float* b) {
    asm volatile(
        "mma.sync.aligned.m16n8k8.row.col.f32.tf32.tf32.f32 "
        "{%0,%1,%2,%3}, {%4,%5,%6,%7}, {%8,%9}, {%0,%1,%2,%3};\n"
        : "+f"(c[0]), "+f"(c[1]), "+f"(c[2]), "+f"(c[3])
        : "r"(__float_as_uint(a[0])), "r"(__float_as_uint(a[1])),
          "r"(__float_as_uint(a[2])), "r"(__float_as_uint(a[3])),
          "r"(__float_as_uint(b[0])), "r"(__float_as_uint(b[1])));
}

// ---------------------------------------------------------------------------
// Elementwise tf32-RNA pre-round (float4), exact-size launch.
// ---------------------------------------------------------------------------
__global__ __launch_bounds__(256) void round_kernel(const float* __restrict__ src,
                                                    float* __restrict__ dst)
{
    int i = (blockIdx.x * 256 + threadIdx.x) * 4;
    float4 v = *(const float4*)(src + i);
    v.x = tf32r(v.x); v.y = tf32r(v.y); v.z = tf32r(v.z); v.w = tf32r(v.w);
    *(float4*)(dst + i) = v;
}

// ---------------------------------------------------------------------------
// Shared GEMM mainloop, BK=32, 2-stage cp.async pipeline.
// CTA 128x128, 8 warps (4x2), warp tile 32x64.
// Inputs pre-rounded to tf32; no cvt in loop. Accumulates into c[2][8][4].
// ---------------------------------------------------------------------------
struct SmemGemm {
    float As[2][128][36];   // pad 36: (4g+t)%32 distinct -> conflict-free
    float Bs[2][32][136];   // pad 136: (8t+g)%32 distinct -> conflict-free
};

__device__ __forceinline__ void gemm_mainloop(
    const float* __restrict__ A, const float* __restrict__ W,
    int m0, int n0, int N, int K, SmemGemm* smp, float c[2][8][4])
{
    const int tid  = threadIdx.x;
    const int lane = tid & 31;
    const int wid  = tid >> 5;
    const int g    = lane >> 2;
    const int t    = lane & 3;
    const int wm   = wid & 3;
    const int wn   = wid >> 2;

    // A slab: 128 rows x 32 cols -> 16B chunks: id = row*8 + c4
    // B slab: 32 rows x 128 cols -> 16B chunks: id = row*32 + c4
    uint32_t a_smem[4], b_smem[4];
    const float* a_gptr[4];
    const float* b_gptr[4];
#pragma unroll
    for (int j = 0; j < 4; j++) {
        int id = tid + 256 * j;
        int row = id >> 3, c4 = (id & 7) * 4;
        a_smem[j] = (uint32_t)__cvta_generic_to_shared(&smp->As[0][row][c4]);
        a_gptr[j] = A + (size_t)(m0 + row) * K + c4;
    }
#pragma unroll
    for (int j = 0; j < 4; j++) {
        int id = tid + 256 * j;
        int row = id >> 5, c4 = (id & 31) * 4;
        b_smem[j] = (uint32_t)__cvta_generic_to_shared(&smp->Bs[0][row][c4]);
        b_gptr[j] = W + (size_t)row * N + n0 + c4;
    }
    const uint32_t aStage = (uint32_t)(sizeof(float) * 128 * 36);
    const uint32_t bStage = (uint32_t)(sizeof(float) * 32 * 136);

    auto issue_slab = [&](int slab, int buf) {
        const int kt = slab << 5;
#pragma unroll
        for (int j = 0; j < 4; j++)
            cp_async16(a_smem[j] + buf * aStage, a_gptr[j] + kt);
#pragma unroll
        for (int j = 0; j < 4; j++)
            cp_async16(b_smem[j] + buf * bStage, b_gptr[j] + (size_t)kt * N);
        cp_commit();
    };

    const int nslab = K >> 5;
    issue_slab(0, 0);

    for (int i = 0; i < nslab; i++) {
        cp_wait0();
        __syncthreads();
        if (i + 1 < nslab) issue_slab(i + 1, (i + 1) & 1);

        const int cb = i & 1;
#pragma unroll
        for (int kk = 0; kk < 4; kk++) {
            float a[2][4];
#pragma unroll
            for (int mf = 0; mf < 2; mf++) {
                const int r = wm * 32 + mf * 16;
                a[mf][0] = smp->As[cb][r + g    ][kk * 8 + t    ];
                a[mf][1] = smp->As[cb][r + g + 8][kk * 8 + t    ];
                a[mf][2] = smp->As[cb][r + g    ][kk * 8 + t + 4];
                a[mf][3] = smp->As[cb][r + g + 8][kk * 8 + t + 4];
            }
            float b[8][2];
#pragma unroll
            for (int nf = 0; nf < 8; nf++) {
                const int cc = wn * 64 + nf * 8 + g;
                b[nf][0] = smp->Bs[cb][kk * 8 + t    ][cc];
                b[nf][1] = smp->Bs[cb][kk * 8 + t + 4][cc];
            }
#pragma unroll
            for (int mf = 0; mf < 2; mf++)
#pragma unroll
                for (int nf = 0; nf < 8; nf++)
                    mma8(c[mf][nf], a[mf], b[nf]);
        }
    }
}

// ---------------------------------------------------------------------------
// Merged QKV GEMM: z = blockIdx.z selects {Wq->Q, Wk->K, Wv->V}.
// Epilogue: (acc + bias) * scale, tf32-rounded.
// Q is scaled by log2e/8 so attention softmax can run in the exp2 domain.
// ---------------------------------------------------------------------------
__global__ __launch_bounds__(256, 2) void qkv_tc(
    const float* __restrict__ A,
    const float* __restrict__ W0, const float* __restrict__ W1p,
    const float* __restrict__ W2p,
    const float* __restrict__ b0, const float* __restrict__ b1p,
    const float* __restrict__ b2p,
    float* __restrict__ C0, float* __restrict__ C1p, float* __restrict__ C2p)
{
    __shared__ SmemGemm smem;
    const int z = blockIdx.z;
    const float* W = (z == 0) ? W0 : (z == 1) ? W1p : W2p;
    const float* bias = (z == 0) ? b0 : (z == 1) ? b1p : b2p;
    float* C = (z == 0) ? C0 : (z == 1) ? C1p : C2p;
    const float scale = (z == 0) ? (0.125f * LOG2E) : 1.0f;

    const int m0 = blockIdx.y * 128;
    const int n0 = blockIdx.x * 128;

    float c[2][8][4];
#pragma unroll
    for (int mf = 0; mf < 2; mf++)
#pragma unroll
        for (int nf = 0; nf < 8; nf++)
#pragma unroll
            for (int i = 0; i < 4; i++) c[mf][nf][i] = 0.f;

    gemm_mainloop(A, W, m0, n0, DM, DM, &smem, c);

    const int lane = threadIdx.x & 31;
    const int wid  = threadIdx.x >> 5;
    const int g    = lane >> 2;
    const int t    = lane & 3;
    const int wm   = wid & 3;
    const int wn   = wid >> 2;
#pragma unroll
    for (int mf = 0; mf < 2; mf++) {
        const int r0 = m0 + wm * 32 + mf * 16 + g;
#pragma unroll
        for (int nf = 0; nf < 8; nf++) {
            const int cc = n0 + wn * 64 + nf * 8 + 2 * t;
            float2 bb = *(const float2*)(bias + cc);
            float v0 = tf32r((c[mf][nf][0] + bb.x) * scale);
            float v1 = tf32r((c[mf][nf][1] + bb.y) * scale);
            float v2 = tf32r((c[mf][nf][2] + bb.x) * scale);
            float v3 = tf32r((c[mf][nf][3] + bb.y) * scale);
            *(float2*)(C + (size_t)r0 * DM + cc)       = make_float2(v0, v1);
            *(float2*)(C + (size_t)(r0 + 8) * DM + cc) = make_float2(v2, v3);
        }
    }
}

// ---------------------------------------------------------------------------
// Generic GEMM for MLP. EPI = 1: bias+ReLU, tf32-rounded output;
//                        EPI = 2: bias+residual, raw fp32 output.
// ---------------------------------------------------------------------------
template <int EPI>
__global__ __launch_bounds__(256, 2) void gemm_tc(
    const float* __restrict__ A, const float* __restrict__ W,
    const float* __restrict__ bias, const float* __restrict__ res,
    float* __restrict__ C, int M, int N, int K)
{
    __shared__ SmemGemm smem;
    const int m0 = blockIdx.y * 128;
    const int n0 = blockIdx.x * 128;

    float c[2][8][4];
#pragma unroll
    for (int mf = 0; mf < 2; mf++)
#pragma unroll
        for (int nf = 0; nf < 8; nf++)
#pragma unroll
            for (int i = 0; i < 4; i++) c[mf][nf][i] = 0.f;

    gemm_mainloop(A, W, m0, n0, N, K, &smem, c);

    const int lane = threadIdx.x & 31;
    const int wid  = threadIdx.x >> 5;
    const int g    = lane >> 2;
    const int t    = lane & 3;
    const int wm   = wid & 3;
    const int wn   = wid >> 2;
#pragma unroll
    for (int mf = 0; mf < 2; mf++) {
        const int r0 = m0 + wm * 32 + mf * 16 + g;
#pragma unroll
        for (int nf = 0; nf < 8; nf++) {
            const int cc = n0 + wn * 64 + nf * 8 + 2 * t;
            float2 bb = *(const float2*)(bias + cc);
            float v0 = c[mf][nf][0] + bb.x;
            float v1 = c[mf][nf][1] + bb.y;
            float v2 = c[mf][nf][2] + bb.x;
            float v3 = c[mf][nf][3] + bb.y;
            if (EPI == 1) {
                v0 = tf32r(fmaxf(v0, 0.f)); v1 = tf32r(fmaxf(v1, 0.f));
                v2 = tf32r(fmaxf(v2, 0.f)); v3 = tf32r(fmaxf(v3, 0.f));
            }
            if (EPI == 2) {
                float2 r0v = *(const float2*)(res + (size_t)r0 * N + cc);
                float2 r1v = *(const float2*)(res + (size_t)(r0 + 8) * N + cc);
                v0 += r0v.x; v1 += r0v.y; v2 += r1v.x; v3 += r1v.y;
            }
            *(float2*)(C + (size_t)r0 * N + cc)       = make_float2(v0, v1);
            *(float2*)(C + (size_t)(r0 + 8) * N + cc) = make_float2(v2, v3);
        }
    }
}

// ---------------------------------------------------------------------------
// Flash attention, TF32 mma. One CTA per (b, h, 128-row q tile).
// 128 threads = 4 warps; warp owns 32 q rows (2 mf tiles of 16).
// Q fragments in registers (staging buffer aliased as P buffer).
// Scores arrive in the exp2 domain (Q pre-scaled by log2e/8) -> exp2f softmax.
// P stored raw fp32 (mma HW truncates to tf32; bias cancels in normalization).
// smem = 106.5 KB -> 2 CTAs/SM.
// ---------------------------------------------------------------------------
__global__ __launch_bounds__(128, 2) void attn_tc(
    const float* __restrict__ Q, const float* __restrict__ K,
    const float* __restrict__ V, float* __restrict__ Ctx)
{
    extern __shared__ float sm[];
    float* Qs = sm;                       // 128 x 68 staging; later aliased as Ps
    float* Ps = sm;                       // 4 warps x 32 x 68 (same 8704 floats)
    float* Ks = sm + 128 * 68;            // 2 x 64 x 68
    float* Vs = Ks + 2 * 64 * 68;         // 2 x 64 x 72

    const int tid  = threadIdx.x;
    const int lane = tid & 31;
    const int wid  = tid >> 5;            // 0..3
    const int g    = lane >> 2;
    const int t    = lane & 3;
    const int b    = blockIdx.z;
    const int h    = blockIdx.y;
    const int q0   = blockIdx.x * 128;
    const int qr   = wid * 32;
    float* Pw = Ps + wid * 32 * 68;

    const uint32_t ksBase = (uint32_t)__cvta_generic_to_shared(Ks);
    const uint32_t vsBase = (uint32_t)__cvta_generic_to_shared(Vs);
    const uint32_t ksStage = (uint32_t)(sizeof(float) * 64 * 68);
    const uint32_t vsStage = (uint32_t)(sizeof(float) * 64 * 72);

    auto issue_kv = [&](int k0, int buf) {
#pragma unroll
        for (int ii = 0; ii < 8; ii++) {
            int idx = tid + 128 * ii;
            int row = idx >> 4, c4 = (idx & 15) * 4;
            size_t gb = (size_t)(b * SS + k0 + row) * DM + h * DH + c4;
            cp_async16(ksBase + buf * ksStage + (uint32_t)((row * 68 + c4) * 4), K + gb);
            cp_async16(vsBase + buf * vsStage + (uint32_t)((row * 72 + c4) * 4), V + gb);
        }
        cp_commit();
    };

    issue_kv(0, 0);

    // Stage Q tile (128 x 64; pre-scaled, pre-rounded), then extract A-frags.
#pragma unroll
    for (int ii = 0; ii < 16; ii++) {
        int idx = tid + 128 * ii;
        int row = idx >> 4, c4 = (idx & 15) * 4;
        float4 v = *(const float4*)(Q + ((size_t)(b * SS + q0 + row) * DM + h * DH + c4));
        *(float4*)&Qs[row * 68 + c4] = v;
    }
    __syncthreads();

    float Qf[8][2][4];
#pragma unroll
    for (int kk = 0; kk < 8; kk++)
#pragma unroll
        for (int mf = 0; mf < 2; mf++) {
            const int r = qr + mf * 16;
            Qf[kk][mf][0] = Qs[(r + g    ) * 68 + kk * 8 + t    ];
            Qf[kk][mf][1] = Qs[(r + g + 8) * 68 + kk * 8 + t    ];
            Qf[kk][mf][2] = Qs[(r + g    ) * 68 + kk * 8 + t + 4];
            Qf[kk][mf][3] = Qs[(r + g + 8) * 68 + kk * 8 + t + 4];
        }
    __syncthreads();   // Qs dead; region becomes Ps

    float o[2][8][4];
#pragma unroll
    for (int mf = 0; mf < 2; mf++)
#pragma unroll
        for (int nf = 0; nf < 8; nf++)
#pragma unroll
            for (int i = 0; i < 4; i++) o[mf][nf][i] = 0.f;
    float mrow[4] = {-1e30f, -1e30f, -1e30f, -1e30f};
    float lrow[4] = {0.f, 0.f, 0.f, 0.f};

    int it = 0;
    for (int k0 = 0; k0 < SS; k0 += 64, it++) {
        cp_wait0();
        __syncthreads();
        const int cb = it & 1;
        if (k0 + 64 < SS) issue_kv(k0 + 64, cb ^ 1);

        const float* Kb = Ks + cb * 64 * 68;
        const float* Vb = Vs + cb * 64 * 72;

        // S = Q @ K^T (exp2-domain scores)
        float s[2][8][4];
#pragma unroll
        for (int mf = 0; mf < 2; mf++)
#pragma unroll
            for (int nf = 0; nf < 8; nf++)
#pragma unroll
                for (int i = 0; i < 4; i++) s[mf][nf][i] = 0.f;

#pragma unroll
        for (int kk = 0; kk < 8; kk++) {
#pragma unroll
            for (int nf = 0; nf < 8; nf++) {
                float bfr[2];
                bfr[0] = Kb[(nf * 8 + g) * 68 + kk * 8 + t    ];
                bfr[1] = Kb[(nf * 8 + g) * 68 + kk * 8 + t + 4];
                mma8(s[0][nf], Qf[kk][0], bfr);
                mma8(s[1][nf], Qf[kk][1], bfr);
            }
        }

        // Online softmax per mf tile (exp2 domain)
#pragma unroll
        for (int mf = 0; mf < 2; mf++) {
            float mx0 = -1e30f, mx1 = -1e30f;
#pragma unroll
            for (int nf = 0; nf < 8; nf++) {
                mx0 = fmaxf(mx0, fmaxf(s[mf][nf][0], s[mf][nf][1]));
                mx1 = fmaxf(mx1, fmaxf(s[mf][nf][2], s[mf][nf][3]));
            }
            mx0 = fmaxf(mx0, __shfl_xor_sync(0xffffffffu, mx0, 1));
            mx0 = fmaxf(mx0, __shfl_xor_sync(0xffffffffu, mx0, 2));
            mx1 = fmaxf(mx1, __shfl_xor_sync(0xffffffffu, mx1, 1));
            mx1 = fmaxf(mx1, __shfl_xor_sync(0xffffffffu, mx1, 2));

            float mn0 = fmaxf(mrow[mf * 2    ], mx0);
            float mn1 = fmaxf(mrow[mf * 2 + 1], mx1);
            float cr0 = exp2f(mrow[mf * 2    ] - mn0);
            float cr1 = exp2f(mrow[mf * 2 + 1] - mn1);
            mrow[mf * 2] = mn0; mrow[mf * 2 + 1] = mn1;

            float sum0 = 0.f, sum1 = 0.f;
#pragma unroll
            for (int nf = 0; nf < 8; nf++) {
                s[mf][nf][0] = exp2f(s[mf][nf][0] - mn0);
                s[mf][nf][1] = exp2f(s[mf][nf][1] - mn0);
                s[mf][nf][2] = exp2f(s[mf][nf][2] - mn1);
                s[mf][nf][3] = exp2f(s[mf][nf][3] - mn1);
                sum0 += s[mf][nf][0] + s[mf][nf][1];
                sum1 += s[mf][nf][2] + s[mf][nf][3];
            }
            sum0 += __shfl_xor_sync(0xffffffffu, sum0, 1);
            sum0 += __shfl_xor_sync(0xffffffffu, sum0, 2);
            sum1 += __shfl_xor_sync(0xffffffffu, sum1, 1);
            sum1 += __shfl_xor_sync(0xffffffffu, sum1, 2);
            lrow[mf * 2]     = lrow[mf * 2]     * cr0 + sum0;
            lrow[mf * 2 + 1] = lrow[mf * 2 + 1] * cr1 + sum1;

#pragma unroll
            for (int nf = 0; nf < 8; nf++) {
                o[mf][nf][0] *= cr0; o[mf][nf][1] *= cr0;
                o[mf][nf][2] *= cr1; o[mf][nf][3] *= cr1;
                // raw fp32 store: mma HW truncates to tf32; bias cancels in O = PV/l
                Pw[(mf * 16 + g    ) * 68 + nf * 8 + 2 * t    ] = s[mf][nf][0];
                Pw[(mf * 16 + g    ) * 68 + nf * 8 + 2 * t + 1] = s[mf][nf][1];
                Pw[(mf * 16 + g + 8) * 68 + nf * 8 + 2 * t    ] = s[mf][nf][2];
                Pw[(mf * 16 + g + 8) * 68 + nf * 8 + 2 * t + 1] = s[mf][nf][3];
            }
        }
        __syncwarp();

        // O += P @ V (V B-frags reused across both mf tiles)
#pragma unroll
        for (int kk = 0; kk < 8; kk++) {
            float a[2][4];
#pragma unroll
            for (int mf = 0; mf < 2; mf++) {
                const int r = mf * 16;
                a[mf][0] = Pw[(r + g    ) * 68 + kk * 8 + t    ];
                a[mf][1] = Pw[(r + g + 8) * 68 + kk * 8 + t    ];
                a[mf][2] = Pw[(r + g    ) * 68 + kk * 8 + t + 4];
                a[mf][3] = Pw[(r + g + 8) * 68 + kk * 8 + t + 4];
            }
#pragma unroll
            for (int nf = 0; nf < 8; nf++) {
                float bfr[2];
                bfr[0] = Vb[(kk * 8 + t    ) * 72 + nf * 8 + g];
                bfr[1] = Vb[(kk * 8 + t + 4) * 72 + nf * 8 + g];
                mma8(o[0][nf], a[0], bfr);
                mma8(o[1][nf], a[1], bfr);
            }
        }
        // next-iter P write guarded by the top-of-loop __syncthreads()
    }

    // Finalize, store context (tf32-rounded: feeds MLP1 A operand)
#pragma unroll
    for (int mf = 0; mf < 2; mf++) {
        const float inv0 = 1.f / lrow[mf * 2];
        const float inv1 = 1.f / lrow[mf * 2 + 1];
        const int row0 = b * SS + q0 + qr + mf * 16 + g;
#pragma unroll
        for (int nf = 0; nf < 8; nf++) {
            const int cc = h * DH + nf * 8 + 2 * t;
            *(float2*)(Ctx + (size_t)row0 * DM + cc) =
                make_float2(tf32r(o[mf][nf][0] * inv0), tf32r(o[mf][nf][1] * inv0));
            *(float2*)(Ctx + (size_t)(row0 + 8) * DM + cc) =
                make_float2(tf32r(o[mf][nf][2] * inv1), tf32r(o[mf][nf][3] * inv1));
        }
    }
}

// ---------------------------------------------------------------------------
// LayerNorm over last dim (768), one block per token row.
// ---------------------------------------------------------------------------
__global__ __launch_bounds__(256) void ln_kernel(
    const float* __restrict__ Hbuf, const float* __restrict__ gamma,
    const float* __restrict__ beta, float* __restrict__ out)
{
    __shared__ float red[16];
    const int row = blockIdx.x;
    const float* hp = Hbuf + (size_t)row * DM;

    float v[3];
    float sum = 0.f, sq = 0.f;
#pragma unroll
    for (int i = 0; i < 3; i++) {
        v[i] = hp[threadIdx.x + 256 * i];
        sum += v[i];
        sq  += v[i] * v[i];
    }
#pragma unroll
    for (int off = 16; off > 0; off >>= 1) {
        sum += __shfl_xor_sync(0xffffffffu, sum, off);
        sq  += __shfl_xor_sync(0xffffffffu, sq,  off);
    }
    const int wid = threadIdx.x >> 5, lane = threadIdx.x & 31;
    if (lane == 0) { red[wid] = sum; red[8 + wid] = sq; }
    __syncthreads();
    float ts = 0.f, tq = 0.f;
#pragma unroll
    for (int w = 0; w < 8; w++) { ts += red[w]; tq += red[8 + w]; }

    const float mean = ts * (1.f / (float)DM);
    const float var  = tq * (1.f / (float)DM) - mean * mean;
    const float rstd = rsqrtf(var + EPS);

#pragma unroll
    for (int i = 0; i < 3; i++) {
        int cIdx = threadIdx.x + 256 * i;
        out[(size_t)row * DM + cIdx] = (v[i] - mean) * rstd * gamma[cIdx] + beta[cIdx];
    }
}

// ---------------------------------------------------------------------------
// Launch
// ---------------------------------------------------------------------------
extern "C" void kernel_launch(void* const* d_in, const int* in_sizes, int n_in,
                              void* d_out, int out_size)
{
    const float* x     = (const float*)d_in[0];
    const float* Wq    = (const float*)d_in[1];
    const float* bq    = (const float*)d_in[2];
    const float* Wk    = (const float*)d_in[3];
    const float* bk    = (const float*)d_in[4];
    const float* Wv    = (const float*)d_in[5];
    const float* bv    = (const float*)d_in[6];
    const float* W1    = (const float*)d_in[7];
    const float* b1    = (const float*)d_in[8];
    const float* W2    = (const float*)d_in[9];
    const float* b2    = (const float*)d_in[10];
    const float* gamma = (const float*)d_in[11];
    const float* beta  = (const float*)d_in[12];
    float* out = (float*)d_out;

    void *pX, *pWq, *pWk, *pWv, *pW1, *pW2;
    void *pQ, *pK, *pV, *pCtx, *pHid, *pH;
    cudaGetSymbolAddress(&pX,   g_X);
    cudaGetSymbolAddress(&pWq,  g_Wq);
    cudaGetSymbolAddress(&pWk,  g_Wk);
    cudaGetSymbolAddress(&pWv,  g_Wv);
    cudaGetSymbolAddress(&pW1,  g_W1);
    cudaGetSymbolAddress(&pW2,  g_W2);
    cudaGetSymbolAddress(&pQ,   g_Q);
    cudaGetSymbolAddress(&pK,   g_K);
    cudaGetSymbolAddress(&pV,   g_V);
    cudaGetSymbolAddress(&pCtx, g_Ctx);
    cudaGetSymbolAddress(&pHid, g_Hid);
    cudaGetSymbolAddress(&pH,   g_H);

    // attn smem: Qs/Ps alias 128*68 + Ks 2*64*68 + Vs 2*64*72 floats = 106496 B
    const int smem_attn =
        (128 * 68 + 2 * 64 * 68 + 2 * 64 * 72) * (int)sizeof(float);
    cudaFuncSetAttribute(attn_tc, cudaFuncAttributeMaxDynamicSharedMemorySize,
                         smem_attn);

    dim3 blk(256);

    // Pre-round activations and weights to tf32 (RNA) once
    round_kernel<<<NTOK * DM / 1024, blk>>>(x,  (float*)pX);
    round_kernel<<<DM * DM / 1024, blk>>>(Wq, (float*)pWq);
    round_kernel<<<DM * DM / 1024, blk>>>(Wk, (float*)pWk);
    round_kernel<<<DM * DM / 1024, blk>>>(Wv, (float*)pWv);
    round_kernel<<<DM * 2 * DM / 1024, blk>>>(W1, (float*)pW1);
    round_kernel<<<2 * DM * DM / 1024, blk>>>(W2, (float*)pW2);

    // Merged QKV projections (z selects weight/output)
    dim3 gQKV(DM / 128, NTOK / 128, 3);  // (6, 64, 3)
    qkv_tc<<<gQKV, blk>>>((const float*)pX,
                          (const float*)pWq, (const float*)pWk, (const float*)pWv,
                          bq, bk, bv,
                          (float*)pQ, (float*)pK, (float*)pV);

    // Attention: q-tile 128 per CTA, 4 warps, 2 CTAs/SM
    dim3 gAttn(SS / 128, HH, BB);     // (16, 12, 4)
    attn_tc<<<gAttn, dim3(128), smem_attn>>>((const float*)pQ, (const float*)pK,
                                             (const float*)pV, (float*)pCtx);

    // MLP
    dim3 gM1(2 * DM / 128, NTOK / 128);  // (12, 64)
    gemm_tc<1><<<gM1, blk>>>((const float*)pCtx, (const float*)pW1, b1, nullptr,
                             (float*)pHid, NTOK, 2 * DM, DM);
    dim3 gM2(DM / 128, NTOK / 128);      // (6, 64)
    gemm_tc<2><<<gM2, blk>>>((const float*)pHid, (const float*)pW2, b2, x,
                             (float*)pH, NTOK, DM, 2 * DM);

    // LayerNorm -> output
    ln_kernel<<<NTOK, blk>>>((const float*)pH, gamma, beta, out);
}

// round 17
// speedup vs baseline: 1.2857x; 1.0147x over previous
#include <cuda_runtime.h>
#include <cuda_bf16.h>
#include <math.h>
#include <stdint.h>

// Problem constants
static constexpr int BB   = 4;
static constexpr int SS   = 2048;
static constexpr int DM   = 768;
static constexpr int HH   = 12;
static constexpr int DH   = 64;
static constexpr int NTOK = BB * SS;          // 8192
static constexpr float EPS = 1e-5f;
static constexpr float LOG2E = 1.4426950408889634f;

// Scratch (device globals: no allocation)
__device__ float g_X  [NTOK * DM];            // tf32-rounded x
__device__ float g_Wq [DM * DM];
__device__ float g_Wk [DM * DM];
__device__ float g_Wv [DM * DM];
__device__ float g_W1 [DM * 2 * DM];
__device__ float g_W2 [2 * DM * DM];
__device__ float g_Q  [NTOK * DM];
__device__ float g_K  [NTOK * DM];
__device__ float g_V  [NTOK * DM];
__device__ float g_Ctx[NTOK * DM];
__device__ float g_Hid[NTOK * 2 * DM];
__device__ float g_H  [NTOK * DM];

// ---------------------------------------------------------------------------
// TF32 / cp.async helpers
// ---------------------------------------------------------------------------
__device__ __forceinline__ float tf32r(float x) {
    uint32_t u;
    asm("cvt.rna.tf32.f32 %0, %1;" : "=r"(u) : "f"(x));
    return __uint_as_float(u);
}

__device__ __forceinline__ void cp_async16(uint32_t dst, const void* src) {
    asm volatile("cp.async.cg.shared.global [%0], [%1], 16;\n" :: "r"(dst), "l"(src));
}
__device__ __forceinline__ void cp_commit() {
    asm volatile("cp.async.commit_group;\n" ::: "memory");
}
__device__ __forceinline__ void cp_wait0() {
    asm volatile("cp.async.wait_group 0;\n" ::: "memory");
}

// D(16x8) += A(16x8) * B(8x8)  tf32 inputs, fp32 accum.
__device__ __forceinline__ void mma8(float* c, const float* a, const float* b) {
    asm volatile(
        "mma.sync.aligned.m16n8k8.row.col.f32.tf32.tf32.f32 "
        "{%0,%1,%2,%3}, {%4,%5,%6,%7}, {%8,%9}, {%0,%1,%2,%3};\n"
        : "+f"(c[0]), "+f"(c[1]), "+f"(c[2]), "+f"(c[3])
        : "r"(__float_as_uint(a[0])), "r"(__float_as_uint(a[1])),
          "r"(__float_as_uint(a[2])), "r"(__float_as_uint(a[3])),
          "r"(__float_as_uint(b[0])), "r"(__float_as_uint(b[1])));
}

// ---------------------------------------------------------------------------
// Elementwise tf32-RNA pre-round (float4), exact-size launch.
// ---------------------------------------------------------------------------
__global__ __launch_bounds__(256) void round_kernel(const float* __restrict__ src,
                                                    float* __restrict__ dst)
{
    int i = (blockIdx.x * 256 + threadIdx.x) * 4;
    float4 v = *(const float4*)(src + i);
    v.x = tf32r(v.x); v.y = tf32r(v.y); v.z = tf32r(v.z); v.w = tf32r(v.w);
    *(float4*)(dst + i) = v;
}

// ---------------------------------------------------------------------------
// Shared GEMM mainloop, BK=32, 2-stage cp.async pipeline.
// CTA 128x128, 4 warps (2x2), warp tile 64x64 -> 1 LDS per mma (crossbar
// no longer co-saturated with tensor pipe).
// Inputs pre-rounded to tf32; no cvt in loop. Accumulates into c[4][8][4].
// ---------------------------------------------------------------------------
struct SmemGemm {
    float As[2][128][36];   // pad 36: (4g+t)%32 distinct -> conflict-free
    float Bs[2][32][136];   // pad 136: (8t+g)%32 distinct -> conflict-free
};

__device__ __forceinline__ void gemm_mainloop(
    const float* __restrict__ A, const float* __restrict__ W,
    int m0, int n0, int N, int K, SmemGemm* smp, float c[4][8][4])
{
    const int tid  = threadIdx.x;        // 0..127
    const int lane = tid & 31;
    const int wid  = tid >> 5;           // 0..3
    const int g    = lane >> 2;
    const int t    = lane & 3;
    const int wm   = wid & 1;            // 2 warps over M (64 each)
    const int wn   = wid >> 1;           // 2 warps over N (64 each)

    const uint32_t aBase = (uint32_t)__cvta_generic_to_shared(&smp->As[0][0][0]);
    const uint32_t bBase = (uint32_t)__cvta_generic_to_shared(&smp->Bs[0][0][0]);
    const uint32_t aStage = (uint32_t)(sizeof(float) * 128 * 36);
    const uint32_t bStage = (uint32_t)(sizeof(float) * 32 * 136);

    // A slab: 128 rows x 32 cols; 128 thr x 8 chunks (row = tid>>3 + 16j)
    // B slab: 32 rows x 128 cols; 128 thr x 8 chunks (row = tid>>5 + 4j)
    const int arow0 = tid >> 3, ac4 = (tid & 7) * 4;
    const int brow0 = tid >> 5, bc4 = (tid & 31) * 4;
    const uint32_t asOff = (uint32_t)((arow0 * 36 + ac4) * 4);
    const uint32_t bsOff = (uint32_t)((brow0 * 136 + bc4) * 4);

    auto issue_slab = [&](int slab, int buf) {
        const float* ag = A + (size_t)(m0 + arow0) * K + ac4 + (slab << 5);
        const float* bg = W + (size_t)(brow0 + (slab << 5)) * N + n0 + bc4;
        uint32_t as = aBase + buf * aStage + asOff;
        uint32_t bs = bBase + buf * bStage + bsOff;
#pragma unroll
        for (int j = 0; j < 8; j++)
            cp_async16(as + (uint32_t)(j * 16 * 36 * 4), ag + (size_t)j * 16 * K);
#pragma unroll
        for (int j = 0; j < 8; j++)
            cp_async16(bs + (uint32_t)(j * 4 * 136 * 4), bg + (size_t)j * 4 * N);
        cp_commit();
    };

    const int nslab = K >> 5;
    issue_slab(0, 0);

    for (int i = 0; i < nslab; i++) {
        cp_wait0();
        __syncthreads();
        if (i + 1 < nslab) issue_slab(i + 1, (i + 1) & 1);

        const int cb = i & 1;
#pragma unroll
        for (int kk = 0; kk < 4; kk++) {
            float a[4][4];
#pragma unroll
            for (int mf = 0; mf < 4; mf++) {
                const int r = wm * 64 + mf * 16;
                a[mf][0] = smp->As[cb][r + g    ][kk * 8 + t    ];
                a[mf][1] = smp->As[cb][r + g + 8][kk * 8 + t    ];
                a[mf][2] = smp->As[cb][r + g    ][kk * 8 + t + 4];
                a[mf][3] = smp->As[cb][r + g + 8][kk * 8 + t + 4];
            }
            float b[8][2];
#pragma unroll
            for (int nf = 0; nf < 8; nf++) {
                const int cc = wn * 64 + nf * 8 + g;
                b[nf][0] = smp->Bs[cb][kk * 8 + t    ][cc];
                b[nf][1] = smp->Bs[cb][kk * 8 + t + 4][cc];
            }
#pragma unroll
            for (int mf = 0; mf < 4; mf++)
#pragma unroll
                for (int nf = 0; nf < 8; nf++)
                    mma8(c[mf][nf], a[mf], b[nf]);
        }
    }
}

// ---------------------------------------------------------------------------
// Merged QKV GEMM: z = blockIdx.z selects {Wq->Q, Wk->K, Wv->V}.
// Epilogue: (acc + bias) * scale, tf32-rounded.
// Q is scaled by log2e/8 so attention softmax can run in the exp2 domain.
// ---------------------------------------------------------------------------
__global__ __launch_bounds__(128, 2) void qkv_tc(
    const float* __restrict__ A,
    const float* __restrict__ W0, const float* __restrict__ W1p,
    const float* __restrict__ W2p,
    const float* __restrict__ b0, const float* __restrict__ b1p,
    const float* __restrict__ b2p,
    float* __restrict__ C0, float* __restrict__ C1p, float* __restrict__ C2p)
{
    __shared__ SmemGemm smem;
    const int z = blockIdx.z;
    const float* W = (z == 0) ? W0 : (z == 1) ? W1p : W2p;
    const float* bias = (z == 0) ? b0 : (z == 1) ? b1p : b2p;
    float* C = (z == 0) ? C0 : (z == 1) ? C1p : C2p;
    const float scale = (z == 0) ? (0.125f * LOG2E) : 1.0f;

    const int m0 = blockIdx.y * 128;
    const int n0 = blockIdx.x * 128;

    float c[4][8][4];
#pragma unroll
    for (int mf = 0; mf < 4; mf++)
#pragma unroll
        for (int nf = 0; nf < 8; nf++)
#pragma unroll
            for (int i = 0; i < 4; i++) c[mf][nf][i] = 0.f;

    gemm_mainloop(A, W, m0, n0, DM, DM, &smem, c);

    const int lane = threadIdx.x & 31;
    const int wid  = threadIdx.x >> 5;
    const int g    = lane >> 2;
    const int t    = lane & 3;
    const int wm   = wid & 1;
    const int wn   = wid >> 1;
#pragma unroll
    for (int mf = 0; mf < 4; mf++) {
        const int r0 = m0 + wm * 64 + mf * 16 + g;
#pragma unroll
        for (int nf = 0; nf < 8; nf++) {
            const int cc = n0 + wn * 64 + nf * 8 + 2 * t;
            float2 bb = *(const float2*)(bias + cc);
            float v0 = tf32r((c[mf][nf][0] + bb.x) * scale);
            float v1 = tf32r((c[mf][nf][1] + bb.y) * scale);
            float v2 = tf32r((c[mf][nf][2] + bb.x) * scale);
            float v3 = tf32r((c[mf][nf][3] + bb.y) * scale);
            *(float2*)(C + (size_t)r0 * DM + cc)       = make_float2(v0, v1);
            *(float2*)(C + (size_t)(r0 + 8) * DM + cc) = make_float2(v2, v3);
        }
    }
}

// ---------------------------------------------------------------------------
// Generic GEMM for MLP. EPI = 1: bias+ReLU, tf32-rounded output;
//                        EPI = 2: bias+residual, raw fp32 output.
// ---------------------------------------------------------------------------
template <int EPI>
__global__ __launch_bounds__(128, 2) void gemm_tc(
    const float* __restrict__ A, const float* __restrict__ W,
    const float* __restrict__ bias, const float* __restrict__ res,
    float* __restrict__ C, int M, int N, int K)
{
    __shared__ SmemGemm smem;
    const int m0 = blockIdx.y * 128;
    const int n0 = blockIdx.x * 128;

    float c[4][8][4];
#pragma unroll
    for (int mf = 0; mf < 4; mf++)
#pragma unroll
        for (int nf = 0; nf < 8; nf++)
#pragma unroll
            for (int i = 0; i < 4; i++) c[mf][nf][i] = 0.f;

    gemm_mainloop(A, W, m0, n0, N, K, &smem, c);

    const int lane = threadIdx.x & 31;
    const int wid  = threadIdx.x >> 5;
    const int g    = lane >> 2;
    const int t    = lane & 3;
    const int wm   = wid & 1;
    const int wn   = wid >> 1;
#pragma unroll
    for (int mf = 0; mf < 4; mf++) {
        const int r0 = m0 + wm * 64 + mf * 16 + g;
#pragma unroll
        for (int nf = 0; nf < 8; nf++) {
            const int cc = n0 + wn * 64 + nf * 8 + 2 * t;
            float2 bb = *(const float2*)(bias + cc);
            float v0 = c[mf][nf][0] + bb.x;
            float v1 = c[mf][nf][1] + bb.y;
            float v2 = c[mf][nf][2] + bb.x;
            float v3 = c[mf][nf][3] + bb.y;
            if (EPI == 1) {
                v0 = tf32r(fmaxf(v0, 0.f)); v1 = tf32r(fmaxf(v1, 0.f));
                v2 = tf32r(fmaxf(v2, 0.f)); v3 = tf32r(fmaxf(v3, 0.f));
            }
            if (EPI == 2) {
                float2 r0v = *(const float2*)(res + (size_t)r0 * N + cc);
                float2 r1v = *(const float2*)(res + (size_t)(r0 + 8) * N + cc);
                v0 += r0v.x; v1 += r0v.y; v2 += r1v.x; v3 += r1v.y;
            }
            *(float2*)(C + (size_t)r0 * N + cc)       = make_float2(v0, v1);
            *(float2*)(C + (size_t)(r0 + 8) * N + cc) = make_float2(v2, v3);
        }
    }
}

// ---------------------------------------------------------------------------
// Flash attention, TF32 mma. One CTA per (b, h, 128-row q tile).
// 128 threads = 4 warps; warp owns 32 q rows (2 mf tiles of 16).
// Q fragments in registers (staging buffer aliased as P buffer).
// Scores in exp2 domain (Q pre-scaled by log2e/8) -> exp2f softmax.
// P stored raw fp32 via float2 (mma HW truncates to tf32; bias cancels).
// smem = 106.5 KB -> 2 CTAs/SM.
// ---------------------------------------------------------------------------
__global__ __launch_bounds__(128, 2) void attn_tc(
    const float* __restrict__ Q, const float* __restrict__ K,
    const float* __restrict__ V, float* __restrict__ Ctx)
{
    extern __shared__ float sm[];
    float* Qs = sm;                       // 128 x 68 staging; later aliased as Ps
    float* Ps = sm;                       // 4 warps x 32 x 68 (same 8704 floats)
    float* Ks = sm + 128 * 68;            // 2 x 64 x 68
    float* Vs = Ks + 2 * 64 * 68;         // 2 x 64 x 72

    const int tid  = threadIdx.x;
    const int lane = tid & 31;
    const int wid  = tid >> 5;            // 0..3
    const int g    = lane >> 2;
    const int t    = lane & 3;
    const int b    = blockIdx.z;
    const int h    = blockIdx.y;
    const int q0   = blockIdx.x * 128;
    const int qr   = wid * 32;
    float* Pw = Ps + wid * 32 * 68;

    const uint32_t ksBase = (uint32_t)__cvta_generic_to_shared(Ks);
    const uint32_t vsBase = (uint32_t)__cvta_generic_to_shared(Vs);
    const uint32_t ksStage = (uint32_t)(sizeof(float) * 64 * 68);
    const uint32_t vsStage = (uint32_t)(sizeof(float) * 64 * 72);

    auto issue_kv = [&](int k0, int buf) {
#pragma unroll
        for (int ii = 0; ii < 8; ii++) {
            int idx = tid + 128 * ii;
            int row = idx >> 4, c4 = (idx & 15) * 4;
            size_t gb = (size_t)(b * SS + k0 + row) * DM + h * DH + c4;
            cp_async16(ksBase + buf * ksStage + (uint32_t)((row * 68 + c4) * 4), K + gb);
            cp_async16(vsBase + buf * vsStage + (uint32_t)((row * 72 + c4) * 4), V + gb);
        }
        cp_commit();
    };

    issue_kv(0, 0);

    // Stage Q tile (128 x 64; pre-scaled, pre-rounded), then extract A-frags.
#pragma unroll
    for (int ii = 0; ii < 16; ii++) {
        int idx = tid + 128 * ii;
        int row = idx >> 4, c4 = (idx & 15) * 4;
        float4 v = *(const float4*)(Q + ((size_t)(b * SS + q0 + row) * DM + h * DH + c4));
        *(float4*)&Qs[row * 68 + c4] = v;
    }
    __syncthreads();

    float Qf[8][2][4];
#pragma unroll
    for (int kk = 0; kk < 8; kk++)
#pragma unroll
        for (int mf = 0; mf < 2; mf++) {
            const int r = qr + mf * 16;
            Qf[kk][mf][0] = Qs[(r + g    ) * 68 + kk * 8 + t    ];
            Qf[kk][mf][1] = Qs[(r + g + 8) * 68 + kk * 8 + t    ];
            Qf[kk][mf][2] = Qs[(r + g    ) * 68 + kk * 8 + t + 4];
            Qf[kk][mf][3] = Qs[(r + g + 8) * 68 + kk * 8 + t + 4];
        }
    __syncthreads();   // Qs dead; region becomes Ps

    float o[2][8][4];
#pragma unroll
    for (int mf = 0; mf < 2; mf++)
#pragma unroll
        for (int nf = 0; nf < 8; nf++)
#pragma unroll
            for (int i = 0; i < 4; i++) o[mf][nf][i] = 0.f;
    float mrow[4] = {-1e30f, -1e30f, -1e30f, -1e30f};
    float lrow[4] = {0.f, 0.f, 0.f, 0.f};

    int it = 0;
    for (int k0 = 0; k0 < SS; k0 += 64, it++) {
        cp_wait0();
        __syncthreads();
        const int cb = it & 1;
        if (k0 + 64 < SS) issue_kv(k0 + 64, cb ^ 1);

        const float* Kb = Ks + cb * 64 * 68;
        const float* Vb = Vs + cb * 64 * 72;

        // S = Q @ K^T (exp2-domain scores)
        float s[2][8][4];
#pragma unroll
        for (int mf = 0; mf < 2; mf++)
#pragma unroll
            for (int nf = 0; nf < 8; nf++)
#pragma unroll
                for (int i = 0; i < 4; i++) s[mf][nf][i] = 0.f;

#pragma unroll
        for (int kk = 0; kk < 8; kk++) {
#pragma unroll
            for (int nf = 0; nf < 8; nf++) {
                float bfr[2];
                bfr[0] = Kb[(nf * 8 + g) * 68 + kk * 8 + t    ];
                bfr[1] = Kb[(nf * 8 + g) * 68 + kk * 8 + t + 4];
                mma8(s[0][nf], Qf[kk][0], bfr);
                mma8(s[1][nf], Qf[kk][1], bfr);
            }
        }

        // Online softmax per mf tile (exp2 domain)
#pragma unroll
        for (int mf = 0; mf < 2; mf++) {
            float mx0 = -1e30f, mx1 = -1e30f;
#pragma unroll
            for (int nf = 0; nf < 8; nf++) {
                mx0 = fmaxf(mx0, fmaxf(s[mf][nf][0], s[mf][nf][1]));
                mx1 = fmaxf(mx1, fmaxf(s[mf][nf][2], s[mf][nf][3]));
            }
            mx0 = fmaxf(mx0, __shfl_xor_sync(0xffffffffu, mx0, 1));
            mx0 = fmaxf(mx0, __shfl_xor_sync(0xffffffffu, mx0, 2));
            mx1 = fmaxf(mx1, __shfl_xor_sync(0xffffffffu, mx1, 1));
            mx1 = fmaxf(mx1, __shfl_xor_sync(0xffffffffu, mx1, 2));

            float mn0 = fmaxf(mrow[mf * 2    ], mx0);
            float mn1 = fmaxf(mrow[mf * 2 + 1], mx1);
            float cr0 = exp2f(mrow[mf * 2    ] - mn0);
            float cr1 = exp2f(mrow[mf * 2 + 1] - mn1);
            mrow[mf * 2] = mn0; mrow[mf * 2 + 1] = mn1;

            float sum0 = 0.f, sum1 = 0.f;
#pragma unroll
            for (int nf = 0; nf < 8; nf++) {
                s[mf][nf][0] = exp2f(s[mf][nf][0] - mn0);
                s[mf][nf][1] = exp2f(s[mf][nf][1] - mn0);
                s[mf][nf][2] = exp2f(s[mf][nf][2] - mn1);
                s[mf][nf][3] = exp2f(s[mf][nf][3] - mn1);
                sum0 += s[mf][nf][0] + s[mf][nf][1];
                sum1 += s[mf][nf][2] + s[mf][nf][3];
            }
            sum0 += __shfl_xor_sync(0xffffffffu, sum0, 1);
            sum0 += __shfl_xor_sync(0xffffffffu, sum0, 2);
            sum1 += __shfl_xor_sync(0xffffffffu, sum1, 1);
            sum1 += __shfl_xor_sync(0xffffffffu, sum1, 2);
            lrow[mf * 2]     = lrow[mf * 2]     * cr0 + sum0;
            lrow[mf * 2 + 1] = lrow[mf * 2 + 1] * cr1 + sum1;

#pragma unroll
            for (int nf = 0; nf < 8; nf++) {
                o[mf][nf][0] *= cr0; o[mf][nf][1] *= cr0;
                o[mf][nf][2] *= cr1; o[mf][nf][3] *= cr1;
                // raw fp32 float2 stores (cols 2t, 2t+1 adjacent)
                *(float2*)&Pw[(mf * 16 + g    ) * 68 + nf * 8 + 2 * t] =
                    make_float2(s[mf][nf][0], s[mf][nf][1]);
                *(float2*)&Pw[(mf * 16 + g + 8) * 68 + nf * 8 + 2 * t] =
                    make_float2(s[mf][nf][2], s[mf][nf][3]);
            }
        }
        __syncwarp();

        // O += P @ V (V B-frags reused across both mf tiles)
#pragma unroll
        for (int kk = 0; kk < 8; kk++) {
            float a[2][4];
#pragma unroll
            for (int mf = 0; mf < 2; mf++) {
                const int r = mf * 16;
                a[mf][0] = Pw[(r + g    ) * 68 + kk * 8 + t    ];
                a[mf][1] = Pw[(r + g + 8) * 68 + kk * 8 + t    ];
                a[mf][2] = Pw[(r + g    ) * 68 + kk * 8 + t + 4];
                a[mf][3] = Pw[(r + g + 8) * 68 + kk * 8 + t + 4];
            }
#pragma unroll
            for (int nf = 0; nf < 8; nf++) {
                float bfr[2];
                bfr[0] = Vb[(kk * 8 + t    ) * 72 + nf * 8 + g];
                bfr[1] = Vb[(kk * 8 + t + 4) * 72 + nf * 8 + g];
                mma8(o[0][nf], a[0], bfr);
                mma8(o[1][nf], a[1], bfr);
            }
        }
        // next-iter P write guarded by the top-of-loop __syncthreads()
    }

    // Finalize, store context (tf32-rounded: feeds MLP1 A operand)
#pragma unroll
    for (int mf = 0; mf < 2; mf++) {
        const float inv0 = 1.f / lrow[mf * 2];
        const float inv1 = 1.f / lrow[mf * 2 + 1];
        const int row0 = b * SS + q0 + qr + mf * 16 + g;
#pragma unroll
        for (int nf = 0; nf < 8; nf++) {
            const int cc = h * DH + nf * 8 + 2 * t;
            *(float2*)(Ctx + (size_t)row0 * DM + cc) =
                make_float2(tf32r(o[mf][nf][0] * inv0), tf32r(o[mf][nf][1] * inv0));
            *(float2*)(Ctx + (size_t)(row0 + 8) * DM + cc) =
                make_float2(tf32r(o[mf][nf][2] * inv1), tf32r(o[mf][nf][3] * inv1));
        }
    }
}

// ---------------------------------------------------------------------------
// LayerNorm over last dim (768), one block per token row.
// ---------------------------------------------------------------------------
__global__ __launch_bounds__(256) void ln_kernel(
    const float* __restrict__ Hbuf, const float* __restrict__ gamma,
    const float* __restrict__ beta, float* __restrict__ out)
{
    __shared__ float red[16];
    const int row = blockIdx.x;
    const float* hp = Hbuf + (size_t)row * DM;

    float v[3];
    float sum = 0.f, sq = 0.f;
#pragma unroll
    for (int i = 0; i < 3; i++) {
        v[i] = hp[threadIdx.x + 256 * i];
        sum += v[i];
        sq  += v[i] * v[i];
    }
#pragma unroll
    for (int off = 16; off > 0; off >>= 1) {
        sum += __shfl_xor_sync(0xffffffffu, sum, off);
        sq  += __shfl_xor_sync(0xffffffffu, sq,  off);
    }
    const int wid = threadIdx.x >> 5, lane = threadIdx.x & 31;
    if (lane == 0) { red[wid] = sum; red[8 + wid] = sq; }
    __syncthreads();
    float ts = 0.f, tq = 0.f;
#pragma unroll
    for (int w = 0; w < 8; w++) { ts += red[w]; tq += red[8 + w]; }

    const float mean = ts * (1.f / (float)DM);
    const float var  = tq * (1.f / (float)DM) - mean * mean;
    const float rstd = rsqrtf(var + EPS);

#pragma unroll
    for (int i = 0; i < 3; i++) {
        int cIdx = threadIdx.x + 256 * i;
        out[(size_t)row * DM + cIdx] = (v[i] - mean) * rstd * gamma[cIdx] + beta[cIdx];
    }
}

// ---------------------------------------------------------------------------
// Launch
// ---------------------------------------------------------------------------
extern "C" void kernel_launch(void* const* d_in, const int* in_sizes, int n_in,
                              void* d_out, int out_size)
{
    const float* x     = (const float*)d_in[0];
    const float* Wq    = (const float*)d_in[1];
    const float* bq    = (const float*)d_in[2];
    const float* Wk    = (const float*)d_in[3];
    const float* bk    = (const float*)d_in[4];
    const float* Wv    = (const float*)d_in[5];
    const float* bv    = (const float*)d_in[6];
    const float* W1    = (const float*)d_in[7];
    const float* b1    = (const float*)d_in[8];
    const float* W2    = (const float*)d_in[9];
    const float* b2    = (const float*)d_in[10];
    const float* gamma = (const float*)d_in[11];
    const float* beta  = (const float*)d_in[12];
    float* out = (float*)d_out;

    void *pX, *pWq, *pWk, *pWv, *pW1, *pW2;
    void *pQ, *pK, *pV, *pCtx, *pHid, *pH;
    cudaGetSymbolAddress(&pX,   g_X);
    cudaGetSymbolAddress(&pWq,  g_Wq);
    cudaGetSymbolAddress(&pWk,  g_Wk);
    cudaGetSymbolAddress(&pWv,  g_Wv);
    cudaGetSymbolAddress(&pW1,  g_W1);
    cudaGetSymbolAddress(&pW2,  g_W2);
    cudaGetSymbolAddress(&pQ,   g_Q);
    cudaGetSymbolAddress(&pK,   g_K);
    cudaGetSymbolAddress(&pV,   g_V);
    cudaGetSymbolAddress(&pCtx, g_Ctx);
    cudaGetSymbolAddress(&pHid, g_Hid);
    cudaGetSymbolAddress(&pH,   g_H);

    // attn smem: Qs/Ps alias 128*68 + Ks 2*64*68 + Vs 2*64*72 floats = 106496 B
    const int smem_attn =
        (128 * 68 + 2 * 64 * 68 + 2 * 64 * 72) * (int)sizeof(float);
    cudaFuncSetAttribute(attn_tc, cudaFuncAttributeMaxDynamicSharedMemorySize,
                         smem_attn);

    dim3 blk256(256);
    dim3 blk128(128);

    // Pre-round activations and weights to tf32 (RNA) once
    round_kernel<<<NTOK * DM / 1024, blk256>>>(x,  (float*)pX);
    round_kernel<<<DM * DM / 1024, blk256>>>(Wq, (float*)pWq);
    round_kernel<<<DM * DM / 1024, blk256>>>(Wk, (float*)pWk);
    round_kernel<<<DM * DM / 1024, blk256>>>(Wv, (float*)pWv);
    round_kernel<<<DM * 2 * DM / 1024, blk256>>>(W1, (float*)pW1);
    round_kernel<<<2 * DM * DM / 1024, blk256>>>(W2, (float*)pW2);

    // Merged QKV projections (z selects weight/output)
    dim3 gQKV(DM / 128, NTOK / 128, 3);  // (6, 64, 3)
    qkv_tc<<<gQKV, blk128>>>((const float*)pX,
                             (const float*)pWq, (const float*)pWk, (const float*)pWv,
                             bq, bk, bv,
                             (float*)pQ, (float*)pK, (float*)pV);

    // Attention: q-tile 128 per CTA, 4 warps, 2 CTAs/SM
    dim3 gAttn(SS / 128, HH, BB);     // (16, 12, 4)
    attn_tc<<<gAttn, blk128, smem_attn>>>((const float*)pQ, (const float*)pK,
                                          (const float*)pV, (float*)pCtx);

    // MLP
    dim3 gM1(2 * DM / 128, NTOK / 128);  // (12, 64)
    gemm_tc<1><<<gM1, blk128>>>((const float*)pCtx, (const float*)pW1, b1, nullptr,
                                (float*)pHid, NTOK, 2 * DM, DM);
    dim3 gM2(DM / 128, NTOK / 128);      // (6, 64)
    gemm_tc<2><<<gM2, blk128>>>((const float*)pHid, (const float*)pW2, b2, x,
                                (float*)pH, NTOK, DM, 2 * DM);

    // LayerNorm -> output
    ln_kernel<<<NTOK, blk256>>>((const float*)pH, gamma, beta, out);
}